// round 7
// baseline (speedup 1.0000x reference)
#include <cuda_runtime.h>
#include <math.h>
#include <stdint.h>

#define NB   4
#define NC   512
#define HWs  4096
#define NA   36864
#define NSORT 65536
#define NIN  6000
#define NWRD 94
#define NPAD 6016
#define NOUTP 300
#define KTOT 4608
#define NCHUNK 288     // K chunks of 16

#define OFF_LOCS 294912
#define OFF_ROIS 884736
#define OFF_INDS 889536
#define OFF_ANCH 890736

typedef unsigned long long u64;

// ---------------- scratch ----------------
__device__ float g_h[(size_t)NB * HWs * NC];   // layout [b][sp][oc]
__device__ float g_w_hi[(size_t)NC * KTOT];
__device__ float g_w_lo[(size_t)NC * KTOT];
__device__ float g_rois[(size_t)NB * NA * 4];
__device__ unsigned char g_valid[NB * NA];
__device__ u64 g_keys[NB * NSORT];
__device__ float g_rois_s[NB * NPAD * 4];
__device__ unsigned char g_valid_s[NB * NPAD];
__device__ u64 g_mask[(size_t)NB * NIN * NWRD];
__device__ unsigned char g_keep[NB * NIN];

static __device__ __forceinline__ uint32_t cvt_tf32(float v) {
    uint32_t r;
    asm("cvt.rna.tf32.f32 %0, %1;" : "=r"(r) : "f"(v));
    return r;
}

// d = a*b + c  (explicit C so chains can start from zero)
#define MMA_TF32(d, a, b, c) \
    asm volatile("mma.sync.aligned.m16n8k8.row.col.f32.tf32.tf32.f32 " \
        "{%0,%1,%2,%3}, {%4,%5,%6,%7}, {%8,%9}, {%10,%11,%12,%13};" \
        : "=f"((d)[0]), "=f"((d)[1]), "=f"((d)[2]), "=f"((d)[3]) \
        : "r"((a)[0]), "r"((a)[1]), "r"((a)[2]), "r"((a)[3]), \
          "r"((b)[0]), "r"((b)[1]), \
          "f"((c)[0]), "f"((c)[1]), "f"((c)[2]), "f"((c)[3]))

// ---------------- weight hi/lo split ----------------
__global__ void prep_w_kernel(const float* __restrict__ w) {
    int gid = blockIdx.x * blockDim.x + threadIdx.x;
    if (gid >= NC * KTOT) return;
    float v = w[gid];
    uint32_t hi = cvt_tf32(v);
    float lo = v - __uint_as_float(hi);
    g_w_hi[gid] = __uint_as_float(hi);
    g_w_lo[gid] = __uint_as_float(cvt_tf32(lo));
}

// ---------------- tf32 mma.sync conv (3-product + register drains) ----------------
// grid (32 sp-tiles, 4 oc-tiles, 4 batch), 256 threads (8 warps, 2x4 warp grid).
__global__ void __launch_bounds__(256) conv_mma_kernel(const float* __restrict__ x,
                                                       const float* __restrict__ bias) {
    __shared__ float sA_hi[128 * 17];
    __shared__ float sA_lo[128 * 17];
    __shared__ float sW_hi[128 * 17];
    __shared__ float sW_lo[128 * 17];

    int tid = threadIdx.x;
    int warp = tid >> 5, lane = tid & 31;
    int gid = lane >> 2, tig = lane & 3;
    int b = blockIdx.z, spt = blockIdx.x, ocg = blockIdx.y;
    int sp0 = spt * 128, oc0 = ocg * 128;
    int wm = warp & 1, wn = warp >> 1;

    float acc[4][4][4];
#pragma unroll
    for (int mf = 0; mf < 4; mf++)
#pragma unroll
        for (int nf = 0; nf < 4; nf++)
#pragma unroll
            for (int q = 0; q < 4; q++) acc[mf][nf][q] = 0.f;

    const float* xb = x + (size_t)b * NC * HWs;

    // loader roles
    int spl = tid & 127;             // A: spatial lane
    int j0 = tid >> 7;               // A: k-parity (0/1)
    int y = (sp0 + spl) >> 6, xq = (sp0 + spl) & 63;
    int ocl = tid >> 1;              // W: oc lane
    int kl0 = (tid & 1) * 8;         // W: k-half

    float vA[8];
    float4 wh0, wh1, wl0, wl1;

    // prologue: prefetch chunk 0
#pragma unroll
    for (int i = 0; i < 8; i++) {
        int kg = j0 + 2 * i;
        int ic = kg / 9, t = kg - ic * 9;
        int yy = y + t / 3 - 1, xx = xq + t % 3 - 1;
        bool ok = ((unsigned)yy < 64u) & ((unsigned)xx < 64u);
        vA[i] = ok ? __ldg(xb + (size_t)ic * HWs + yy * 64 + xx) : 0.f;
    }
    {
        const float4* ph = (const float4*)(g_w_hi + (size_t)(oc0 + ocl) * KTOT + kl0);
        const float4* pl = (const float4*)(g_w_lo + (size_t)(oc0 + ocl) * KTOT + kl0);
        wh0 = ph[0]; wh1 = ph[1]; wl0 = pl[0]; wl1 = pl[1];
    }

    for (int c = 0; c < NCHUNK; c++) {
        // store prefetched chunk into smem (convert A on the fly)
#pragma unroll
        for (int i = 0; i < 8; i++) {
            int j = j0 + 2 * i;
            uint32_t hi = cvt_tf32(vA[i]);
            float lo = vA[i] - __uint_as_float(hi);
            sA_hi[spl * 17 + j] = __uint_as_float(hi);
            sA_lo[spl * 17 + j] = __uint_as_float(cvt_tf32(lo));
        }
        {
            float* dh = &sW_hi[ocl * 17 + kl0];
            float* dl = &sW_lo[ocl * 17 + kl0];
            dh[0] = wh0.x; dh[1] = wh0.y; dh[2] = wh0.z; dh[3] = wh0.w;
            dh[4] = wh1.x; dh[5] = wh1.y; dh[6] = wh1.z; dh[7] = wh1.w;
            dl[0] = wl0.x; dl[1] = wl0.y; dl[2] = wl0.z; dl[3] = wl0.w;
            dl[4] = wl1.x; dl[5] = wl1.y; dl[6] = wl1.z; dl[7] = wl1.w;
        }
        __syncthreads();

        // prefetch next chunk (LDG latency hidden under MMAs below)
        if (c + 1 < NCHUNK) {
            int cn = c + 1;
#pragma unroll
            for (int i = 0; i < 8; i++) {
                int kg = cn * 16 + j0 + 2 * i;
                int ic = kg / 9, t = kg - ic * 9;
                int yy = y + t / 3 - 1, xx = xq + t % 3 - 1;
                bool ok = ((unsigned)yy < 64u) & ((unsigned)xx < 64u);
                vA[i] = ok ? __ldg(xb + (size_t)ic * HWs + yy * 64 + xx) : 0.f;
            }
            const float4* ph = (const float4*)(g_w_hi + (size_t)(oc0 + ocl) * KTOT + cn * 16 + kl0);
            const float4* pl = (const float4*)(g_w_lo + (size_t)(oc0 + ocl) * KTOT + cn * 16 + kl0);
            wh0 = ph[0]; wh1 = ph[1]; wl0 = pl[0]; wl1 = pl[1];
        }

        // MMA on current chunk: per k-step, fresh tensor chain of 3 products,
        // then drain into fp32 register accumulators (rn adds).
#pragma unroll
        for (int ks = 0; ks < 2; ks++) {
            int kb = ks * 8;
            uint32_t Ah[4][4], Al[4][4], Bh[4][2], Bl[4][2];
#pragma unroll
            for (int mf = 0; mf < 4; mf++) {
                int ar = wm * 64 + mf * 16 + gid;
                Ah[mf][0] = __float_as_uint(sA_hi[ar * 17 + kb + tig]);
                Ah[mf][1] = __float_as_uint(sA_hi[(ar + 8) * 17 + kb + tig]);
                Ah[mf][2] = __float_as_uint(sA_hi[ar * 17 + kb + tig + 4]);
                Ah[mf][3] = __float_as_uint(sA_hi[(ar + 8) * 17 + kb + tig + 4]);
                Al[mf][0] = __float_as_uint(sA_lo[ar * 17 + kb + tig]);
                Al[mf][1] = __float_as_uint(sA_lo[(ar + 8) * 17 + kb + tig]);
                Al[mf][2] = __float_as_uint(sA_lo[ar * 17 + kb + tig + 4]);
                Al[mf][3] = __float_as_uint(sA_lo[(ar + 8) * 17 + kb + tig + 4]);
            }
#pragma unroll
            for (int nf = 0; nf < 4; nf++) {
                int bc = wn * 32 + nf * 8 + gid;
                Bh[nf][0] = __float_as_uint(sW_hi[bc * 17 + kb + tig]);
                Bh[nf][1] = __float_as_uint(sW_hi[bc * 17 + kb + tig + 4]);
                Bl[nf][0] = __float_as_uint(sW_lo[bc * 17 + kb + tig]);
                Bl[nf][1] = __float_as_uint(sW_lo[bc * 17 + kb + tig + 4]);
            }
            const float zero4[4] = {0.f, 0.f, 0.f, 0.f};
#pragma unroll
            for (int mf = 0; mf < 4; mf++)
#pragma unroll
                for (int nf = 0; nf < 4; nf++) {
                    float d[4];
                    MMA_TF32(d, Ah[mf], Bh[nf], zero4);
                    MMA_TF32(d, Ah[mf], Bl[nf], d);
                    MMA_TF32(d, Al[mf], Bh[nf], d);
#pragma unroll
                    for (int q = 0; q < 4; q++) acc[mf][nf][q] += d[q];
                }
        }
        __syncthreads();
    }

    // epilogue: bias + relu, write g_h[b][sp][oc]
#pragma unroll
    for (int nf = 0; nf < 4; nf++) {
        int col = oc0 + wn * 32 + nf * 8 + 2 * tig;
        float bv0 = __ldg(bias + col), bv1 = __ldg(bias + col + 1);
#pragma unroll
        for (int mf = 0; mf < 4; mf++) {
            int row = sp0 + wm * 64 + mf * 16 + gid;
            size_t b0 = ((size_t)b * HWs + row) * NC + col;
            size_t b1 = ((size_t)b * HWs + row + 8) * NC + col;
            g_h[b0]     = fmaxf(acc[mf][nf][0] + bv0, 0.f);
            g_h[b0 + 1] = fmaxf(acc[mf][nf][1] + bv1, 0.f);
            g_h[b1]     = fmaxf(acc[mf][nf][2] + bv0, 0.f);
            g_h[b1 + 1] = fmaxf(acc[mf][nf][3] + bv1, 0.f);
        }
    }
}

// ---------------- helpers ----------------
__device__ __forceinline__ unsigned int fdesc(float f) {
    unsigned int u = __float_as_uint(f);
    unsigned int asc = (u & 0x80000000u) ? ~u : (u | 0x80000000u);
    return ~asc;
}
__device__ __forceinline__ void base_anchor(int a, float& y1, float& x1, float& y2, float& x2) {
    int ri = a / 3, si = a % 3;
    double ratio = (ri == 0) ? 0.5 : (ri == 1 ? 1.0 : 2.0);
    double scale = (si == 0) ? 8.0 : (si == 1 ? 16.0 : 32.0);
    double h = 16.0 * scale * sqrt(ratio);
    double w = 16.0 * scale * sqrt(1.0 / ratio);
    y1 = (float)(8.0 - h * 0.5); x1 = (float)(8.0 - w * 0.5);
    y2 = (float)(8.0 + h * 0.5); x2 = (float)(8.0 + w * 0.5);
}

// ---------------- 1x1 heads + softmax + decode + sort-key pack ----------------
__global__ void __launch_bounds__(128) heads_kernel(const float* __restrict__ sw,
                                                    const float* __restrict__ sb,
                                                    const float* __restrict__ lw,
                                                    const float* __restrict__ lb,
                                                    float* __restrict__ out) {
    __shared__ float s_w[128 * 54];
    int b = blockIdx.y;
    int pos = blockIdx.x * 128 + threadIdx.x;

    float acc[54];
#pragma unroll
    for (int o = 0; o < 54; o++) acc[o] = 0.f;

    for (int c0 = 0; c0 < NC; c0 += 128) {
        __syncthreads();
        for (int idx = threadIdx.x; idx < 128 * 54; idx += 128) {
            int o = idx / 128, c = idx % 128;
            float v = (o < 18) ? sw[o * 512 + c0 + c] : lw[(o - 18) * 512 + c0 + c];
            s_w[c * 54 + o] = v;
        }
        __syncthreads();
        const float4* hp4 = (const float4*)(g_h + ((size_t)b * HWs + pos) * NC + c0);
        for (int c4 = 0; c4 < 32; c4++) {
            float4 v = hp4[c4];
            const float* w0 = &s_w[(c4 * 4 + 0) * 54];
            const float* w1 = &s_w[(c4 * 4 + 1) * 54];
            const float* w2 = &s_w[(c4 * 4 + 2) * 54];
            const float* w3 = &s_w[(c4 * 4 + 3) * 54];
#pragma unroll
            for (int o = 0; o < 54; o++) {
                acc[o] = fmaf(v.x, w0[o], acc[o]);
                acc[o] = fmaf(v.y, w1[o], acc[o]);
                acc[o] = fmaf(v.z, w2[o], acc[o]);
                acc[o] = fmaf(v.w, w3[o], acc[o]);
            }
        }
    }
#pragma unroll
    for (int o = 0; o < 18; o++) acc[o] += sb[o];
#pragma unroll
    for (int j = 0; j < 36; j++) acc[18 + j] += lb[j];

    float* os = out + (size_t)(b * HWs + pos) * 18;
#pragma unroll
    for (int o = 0; o < 18; o++) os[o] = acc[o];
    float* ol = out + OFF_LOCS + (size_t)(b * HWs + pos) * 36;
#pragma unroll
    for (int j = 0; j < 36; j++) ol[j] = acc[18 + j];

    int y = pos >> 6, xq = pos & 63;
    float fy = (float)(y * 16), fx = (float)(xq * 16);
#pragma unroll
    for (int a = 0; a < 9; a++) {
        float by1, bx1, by2, bx2;
        base_anchor(a, by1, bx1, by2, bx2);
        float ay1 = fy + by1, ax1 = fx + bx1, ay2 = fy + by2, ax2 = fx + bx2;
        float hA = ay2 - ay1, wA = ax2 - ax1;
        float cy = ay1 + 0.5f * hA, cx = ax1 + 0.5f * wA;
        float dy = acc[18 + 4 * a + 0], dx = acc[18 + 4 * a + 1];
        float dh = acc[18 + 4 * a + 2], dw = acc[18 + 4 * a + 3];
        float cty = dy * hA + cy, ctx = dx * wA + cx;
        float th = expf(dh) * hA, tw = expf(dw) * wA;
        float y1 = cty - 0.5f * th, x1 = ctx - 0.5f * tw;
        float y2 = cty + 0.5f * th, x2 = ctx + 0.5f * tw;
        y1 = fminf(fmaxf(y1, 0.f), 1024.f);
        y2 = fminf(fmaxf(y2, 0.f), 1024.f);
        x1 = fminf(fmaxf(x1, 0.f), 1024.f);
        x2 = fminf(fmaxf(x2, 0.f), 1024.f);
        bool valid = (y2 - y1 >= 16.f) && (x2 - x1 >= 16.f);

        float s0 = acc[2 * a], s1 = acc[2 * a + 1];
        float m = fmaxf(s0, s1);
        float e0 = expf(s0 - m), e1 = expf(s1 - m);
        float fg = e1 / (e0 + e1);
        float skey = valid ? fg : -INFINITY;

        int r = pos * 9 + a;
        size_t ro = ((size_t)b * NA + r) * 4;
        g_rois[ro + 0] = y1; g_rois[ro + 1] = x1;
        g_rois[ro + 2] = y2; g_rois[ro + 3] = x2;
        g_valid[b * NA + r] = valid ? 1 : 0;
        g_keys[(size_t)b * NSORT + r] = ((u64)fdesc(skey) << 32) | (unsigned)r;
    }
}

__global__ void pad_keys_kernel() {
    int gid = blockIdx.x * blockDim.x + threadIdx.x;
    int per = NSORT - NA;
    if (gid >= NB * per) return;
    int b = gid / per, i = NA + gid % per;
    g_keys[(size_t)b * NSORT + i] = ~0ull;
}

// ---------------- bitonic sort ----------------
__global__ void __launch_bounds__(1024) bitonic_local_sort() {
    __shared__ u64 s[4096];
    int base = blockIdx.x * 4096;
#pragma unroll
    for (int m = 0; m < 4; m++) s[threadIdx.x + 1024 * m] = g_keys[base + threadIdx.x + 1024 * m];
    for (int k = 2; k <= 4096; k <<= 1) {
        for (int j = k >> 1; j > 0; j >>= 1) {
            __syncthreads();
#pragma unroll
            for (int m = 0; m < 4; m++) {
                int i = threadIdx.x + 1024 * m;
                int p = i ^ j;
                if (p > i) {
                    int lidx = (base + i) & (NSORT - 1);
                    bool asc = ((lidx & k) == 0);
                    u64 av = s[i], bv = s[p];
                    if (asc ? (av > bv) : (av < bv)) { s[i] = bv; s[p] = av; }
                }
            }
        }
    }
    __syncthreads();
#pragma unroll
    for (int m = 0; m < 4; m++) g_keys[base + threadIdx.x + 1024 * m] = s[threadIdx.x + 1024 * m];
}

__global__ void __launch_bounds__(256) bitonic_global_step(int k, int j) {
    int gid = blockIdx.x * blockDim.x + threadIdx.x;
    int seg = gid >> 16, idx = gid & (NSORT - 1);
    int p = idx ^ j;
    if (p > idx) {
        bool asc = ((idx & k) == 0);
        u64* bptr = g_keys + ((size_t)seg << 16);
        u64 av = bptr[idx], bv = bptr[p];
        if (asc ? (av > bv) : (av < bv)) { bptr[idx] = bv; bptr[p] = av; }
    }
}

__global__ void __launch_bounds__(1024) bitonic_local_merge(int k) {
    __shared__ u64 s[4096];
    int base = blockIdx.x * 4096;
    bool asc = (((base & (NSORT - 1)) & k) == 0);
#pragma unroll
    for (int m = 0; m < 4; m++) s[threadIdx.x + 1024 * m] = g_keys[base + threadIdx.x + 1024 * m];
    for (int j = 2048; j > 0; j >>= 1) {
        __syncthreads();
#pragma unroll
        for (int m = 0; m < 4; m++) {
            int i = threadIdx.x + 1024 * m;
            int p = i ^ j;
            if (p > i) {
                u64 av = s[i], bv = s[p];
                if (asc ? (av > bv) : (av < bv)) { s[i] = bv; s[p] = av; }
            }
        }
    }
    __syncthreads();
#pragma unroll
    for (int m = 0; m < 4; m++) g_keys[base + threadIdx.x + 1024 * m] = s[threadIdx.x + 1024 * m];
}

__global__ void gather_kernel() {
    int gid = blockIdx.x * blockDim.x + threadIdx.x;
    if (gid >= NB * NIN) return;
    int b = gid / NIN, i = gid % NIN;
    u64 key = g_keys[(size_t)b * NSORT + i];
    unsigned r = (unsigned)(key & 0xffffffffu);
    size_t src = ((size_t)b * NA + r) * 4;
    size_t dst = ((size_t)b * NPAD + i) * 4;
    g_rois_s[dst + 0] = g_rois[src + 0];
    g_rois_s[dst + 1] = g_rois[src + 1];
    g_rois_s[dst + 2] = g_rois[src + 2];
    g_rois_s[dst + 3] = g_rois[src + 3];
    g_valid_s[b * NPAD + i] = g_valid[b * NA + r];
}

__global__ void __launch_bounds__(64) mask_kernel() {
    int rb = blockIdx.x, cb = blockIdx.y, b = blockIdx.z;
    if (cb < rb) return;
    __shared__ float4 sj[64];
    int u = threadIdx.x;
    const float4* rs = (const float4*)g_rois_s;
    sj[u] = rs[(size_t)b * NPAD + cb * 64 + u];
    __syncthreads();
    int i = rb * 64 + u;
    if (i >= NIN) return;
    float4 bi = rs[(size_t)b * NPAD + i];
    float ai = (bi.z - bi.x) * (bi.w - bi.y);
    u64 bits = 0;
#pragma unroll 8
    for (int q = 0; q < 64; q++) {
        int jj = cb * 64 + q;
        if (jj > i) {
            float4 bj = sj[q];
            float yy1 = fmaxf(bi.x, bj.x), xx1 = fmaxf(bi.y, bj.y);
            float yy2 = fminf(bi.z, bj.z), xx2 = fminf(bi.w, bj.w);
            float inter = fmaxf(yy2 - yy1, 0.f) * fmaxf(xx2 - xx1, 0.f);
            float aj = (bj.z - bj.x) * (bj.w - bj.y);
            float iou = inter / (ai + aj - inter + 1e-9f);
            if (iou > 0.7f) bits |= (1ull << q);
        }
    }
    g_mask[((size_t)b * NIN + i) * NWRD + cb] = bits;
}

__global__ void __launch_bounds__(32) nms_scan_kernel() {
    int b = blockIdx.x;
    int lane = threadIdx.x;
    const u64* mask = g_mask + (size_t)b * NIN * NWRD;
    const unsigned char* vs = g_valid_s + b * NPAD;
    unsigned char* keep = g_keep + b * NIN;
    int w0 = lane, w1 = lane + 32, w2 = lane + 64;
    bool has2 = (w2 < NWRD);
    u64 r0 = 0, r1 = 0, r2 = 0;
    u64 bufA[8][3], bufB[8][3];
    unsigned char vA[8], vB[8];
#pragma unroll
    for (int t = 0; t < 8; t++) {
        const u64* row = mask + (size_t)t * NWRD;
        bufA[t][0] = row[w0]; bufA[t][1] = row[w1];
        bufA[t][2] = has2 ? row[w2] : 0;
        vA[t] = vs[t];
    }
    for (int base = 0; base < NIN; base += 16) {
#pragma unroll
        for (int t = 0; t < 8; t++) {
            int ri = base + 8 + t;
            if (ri < NIN) {
                const u64* row = mask + (size_t)ri * NWRD;
                bufB[t][0] = row[w0]; bufB[t][1] = row[w1];
                bufB[t][2] = has2 ? row[w2] : 0;
                vB[t] = vs[ri];
            } else { bufB[t][0] = bufB[t][1] = bufB[t][2] = 0; vB[t] = 0; }
        }
#pragma unroll
        for (int t = 0; t < 8; t++) {
            int i = base + t;
            int iw = i >> 6;
            int sel = iw >> 5, owner = iw & 31;
            u64 myw = (sel == 0) ? r0 : ((sel == 1) ? r1 : r2);
            u64 wv = __shfl_sync(0xffffffffu, myw, owner);
            bool alive = vA[t] && !((wv >> (i & 63)) & 1ull);
            if (alive) { r0 |= bufA[t][0]; r1 |= bufA[t][1]; r2 |= bufA[t][2]; }
            if (lane == 0) keep[i] = alive ? 1 : 0;
        }
#pragma unroll
        for (int t = 0; t < 8; t++) {
            int ri = base + 16 + t;
            if (ri < NIN) {
                const u64* row = mask + (size_t)ri * NWRD;
                bufA[t][0] = row[w0]; bufA[t][1] = row[w1];
                bufA[t][2] = has2 ? row[w2] : 0;
                vA[t] = vs[ri];
            } else { bufA[t][0] = bufA[t][1] = bufA[t][2] = 0; vA[t] = 0; }
        }
#pragma unroll
        for (int t = 0; t < 8; t++) {
            int i = base + 8 + t;
            if (i >= NIN) break;
            int iw = i >> 6;
            int sel = iw >> 5, owner = iw & 31;
            u64 myw = (sel == 0) ? r0 : ((sel == 1) ? r1 : r2);
            u64 wv = __shfl_sync(0xffffffffu, myw, owner);
            bool alive = vB[t] && !((wv >> (i & 63)) & 1ull);
            if (alive) { r0 |= bufB[t][0]; r1 |= bufB[t][1]; r2 |= bufB[t][2]; }
            if (lane == 0) keep[i] = alive ? 1 : 0;
        }
    }
}

__global__ void misc_kernel(float* __restrict__ out) {
    int gid = blockIdx.x * blockDim.x + threadIdx.x;
    if (gid < NB * NOUTP * 4) out[OFF_ROIS + gid] = 0.f;
    if (gid < NB * NOUTP) out[OFF_INDS + gid] = (float)(gid / NOUTP);
}

__global__ void anchors_kernel(float* __restrict__ out) {
    int r = blockIdx.x * blockDim.x + threadIdx.x;
    if (r >= NA) return;
    int p = r / 9, a = r % 9;
    int y = p / 64, x = p % 64;
    float by1, bx1, by2, bx2;
    base_anchor(a, by1, bx1, by2, bx2);
    float fy = (float)(y * 16), fx = (float)(x * 16);
    float* o = out + OFF_ANCH + (size_t)r * 4;
    o[0] = fy + by1; o[1] = fx + bx1; o[2] = fy + by2; o[3] = fx + bx2;
}

__global__ void __launch_bounds__(256) finalize_kernel(float* __restrict__ out) {
    int b = blockIdx.x;
    int tid = threadIdx.x;
    __shared__ int ssum[256];
    const unsigned char* keep = g_keep + b * NIN;
    unsigned char kl[24];
    int start = tid * 24;
    int cnt = 0;
#pragma unroll
    for (int t = 0; t < 24; t++) {
        int i = start + t;
        kl[t] = (i < NIN) ? keep[i] : 0;
        cnt += kl[t];
    }
    ssum[tid] = cnt;
    __syncthreads();
    for (int off = 1; off < 256; off <<= 1) {
        int v = (tid >= off) ? ssum[tid - off] : 0;
        __syncthreads();
        ssum[tid] += v;
        __syncthreads();
    }
    int r = ssum[tid] - cnt;
    const float4* rs = (const float4*)g_rois_s;
#pragma unroll
    for (int t = 0; t < 24; t++) {
        if (kl[t]) {
            if (r < NOUTP) {
                int i = start + t;
                float4 bx = rs[(size_t)b * NPAD + i];
                float* o = out + OFF_ROIS + (size_t)(b * NOUTP + r) * 4;
                o[0] = bx.x; o[1] = bx.y; o[2] = bx.z; o[3] = bx.w;
            }
            r++;
        }
    }
}

// ---------------- launch ----------------
extern "C" void kernel_launch(void* const* d_in, const int* in_sizes, int n_in,
                              void* d_out, int out_size) {
    const float* x       = (const float*)d_in[0];
    const float* conv_w  = (const float*)d_in[1];
    const float* conv_b  = (const float*)d_in[2];
    const float* score_w = (const float*)d_in[3];
    const float* score_b = (const float*)d_in[4];
    const float* loc_w   = (const float*)d_in[5];
    const float* loc_b   = (const float*)d_in[6];
    float* out = (float*)d_out;

    prep_w_kernel<<<(NC * KTOT + 255) / 256, 256>>>(conv_w);
    conv_mma_kernel<<<dim3(32, 4, NB), 256>>>(x, conv_b);
    heads_kernel<<<dim3(32, NB), 128>>>(score_w, score_b, loc_w, loc_b, out);
    pad_keys_kernel<<<(NB * (NSORT - NA) + 255) / 256, 256>>>();

    bitonic_local_sort<<<NB * NSORT / 4096, 1024>>>();
    for (int k = 8192; k <= NSORT; k <<= 1) {
        for (int j = k >> 1; j >= 4096; j >>= 1)
            bitonic_global_step<<<NB * NSORT / 256, 256>>>(k, j);
        bitonic_local_merge<<<NB * NSORT / 4096, 1024>>>(k);
    }

    gather_kernel<<<(NB * NIN + 255) / 256, 256>>>();
    mask_kernel<<<dim3(NWRD, NWRD, NB), 64>>>();
    nms_scan_kernel<<<NB, 32>>>();
    misc_kernel<<<(NB * NOUTP * 4 + 255) / 256, 256>>>(out);
    anchors_kernel<<<(NA + 255) / 256, 256>>>(out);
    finalize_kernel<<<NB, 256>>>(out);
}

// round 8
// speedup vs baseline: 1.5845x; 1.5845x over previous
#include <cuda_runtime.h>
#include <math.h>
#include <stdint.h>

#define NB   4
#define NC   512
#define HWs  4096
#define NA   36864
#define NSORT 65536
#define NIN  6000
#define NWRD 94
#define NPAD 6016
#define NOUTP 300
#define KTOT 4608
#define NCHUNK 288     // K chunks of 16

#define OFF_LOCS 294912
#define OFF_ROIS 884736
#define OFF_INDS 889536
#define OFF_ANCH 890736

typedef unsigned long long u64;

// ---------------- scratch ----------------
__device__ float g_h[(size_t)NB * HWs * NC];   // layout [b][sp][oc]
__device__ float g_rois[(size_t)NB * NA * 4];
__device__ unsigned char g_valid[NB * NA];
__device__ u64 g_keys[NB * NSORT];
__device__ float g_rois_s[NB * NPAD * 4];
__device__ unsigned char g_valid_s[NB * NPAD];
__device__ u64 g_mask[(size_t)NB * NIN * NWRD];
__device__ unsigned char g_keep[NB * NIN];

// ---------------- FFMA implicit-GEMM conv (128x128 tile, 8x8 micro-tile) ----------------
// grid (32 sp-tiles, 4 oc-tiles, 4 batch), 256 threads.
__global__ void __launch_bounds__(256, 2) conv_ffma_kernel(const float* __restrict__ x,
                                                           const float* __restrict__ w,
                                                           const float* __restrict__ bias) {
    __shared__ float sA[16][128];
    __shared__ float sW[16][128];

    int tid = threadIdx.x;
    int b = blockIdx.z, spt = blockIdx.x, ocg = blockIdx.y;
    int sp0 = spt * 128, oc0 = ocg * 128;
    int tx = tid & 15, ty = tid >> 4;

    float acc[8][8];
#pragma unroll
    for (int i = 0; i < 8; i++)
#pragma unroll
        for (int j = 0; j < 8; j++) acc[i][j] = 0.f;

    const float* xb = x + (size_t)b * NC * HWs;

    // loader roles (A: im2col gather; W: direct fp32)
    int spl = tid & 127;             // A: spatial lane
    int j0 = tid >> 7;               // A: k-parity (0/1)
    int y = (sp0 + spl) >> 6, xq = (sp0 + spl) & 63;
    int ocl = tid >> 1;              // W: oc lane
    int kl0 = (tid & 1) * 8;         // W: k-half

    float vA[8];
    float4 w0r, w1r;

    // prologue: prefetch chunk 0
#pragma unroll
    for (int i = 0; i < 8; i++) {
        int kg = j0 + 2 * i;
        int ic = kg / 9, t = kg - ic * 9;
        int yy = y + t / 3 - 1, xx = xq + t % 3 - 1;
        bool ok = ((unsigned)yy < 64u) & ((unsigned)xx < 64u);
        vA[i] = ok ? __ldg(xb + (size_t)ic * HWs + yy * 64 + xx) : 0.f;
    }
    {
        const float4* pw = (const float4*)(w + (size_t)(oc0 + ocl) * KTOT + kl0);
        w0r = pw[0]; w1r = pw[1];
    }

    for (int c = 0; c < NCHUNK; c++) {
        // store prefetched chunk into smem
#pragma unroll
        for (int i = 0; i < 8; i++) sA[j0 + 2 * i][spl] = vA[i];
        sW[kl0 + 0][ocl] = w0r.x; sW[kl0 + 1][ocl] = w0r.y;
        sW[kl0 + 2][ocl] = w0r.z; sW[kl0 + 3][ocl] = w0r.w;
        sW[kl0 + 4][ocl] = w1r.x; sW[kl0 + 5][ocl] = w1r.y;
        sW[kl0 + 6][ocl] = w1r.z; sW[kl0 + 7][ocl] = w1r.w;
        __syncthreads();

        // prefetch next chunk (LDG latency hidden under FMAs below)
        if (c + 1 < NCHUNK) {
            int cn = c + 1;
#pragma unroll
            for (int i = 0; i < 8; i++) {
                int kg = cn * 16 + j0 + 2 * i;
                int ic = kg / 9, t = kg - ic * 9;
                int yy = y + t / 3 - 1, xx = xq + t % 3 - 1;
                bool ok = ((unsigned)yy < 64u) & ((unsigned)xx < 64u);
                vA[i] = ok ? __ldg(xb + (size_t)ic * HWs + yy * 64 + xx) : 0.f;
            }
            const float4* pw = (const float4*)(w + (size_t)(oc0 + ocl) * KTOT + cn * 16 + kl0);
            w0r = pw[0]; w1r = pw[1];
        }

        // compute: 16 k-steps x (4 LDS.128 + 64 FFMA)
#pragma unroll
        for (int k = 0; k < 16; k++) {
            float4 a0 = *(const float4*)&sA[k][tx * 4];
            float4 a1 = *(const float4*)&sA[k][tx * 4 + 64];
            float4 b0 = *(const float4*)&sW[k][ty * 4];
            float4 b1 = *(const float4*)&sW[k][ty * 4 + 64];
            float av[8] = {a0.x, a0.y, a0.z, a0.w, a1.x, a1.y, a1.z, a1.w};
            float bv[8] = {b0.x, b0.y, b0.z, b0.w, b1.x, b1.y, b1.z, b1.w};
#pragma unroll
            for (int i = 0; i < 8; i++)
#pragma unroll
                for (int j = 0; j < 8; j++)
                    acc[i][j] = fmaf(av[i], bv[j], acc[i][j]);
        }
        __syncthreads();
    }

    // epilogue: bias + relu, vectorized writes to g_h[b][sp][oc]
    float4 bv0 = *(const float4*)&bias[oc0 + ty * 4];
    float4 bv1 = *(const float4*)&bias[oc0 + ty * 4 + 64];
#pragma unroll
    for (int i = 0; i < 8; i++) {
        int sp = sp0 + ((i < 4) ? (tx * 4 + i) : (64 + tx * 4 + i - 4));
        float* hp = g_h + ((size_t)b * HWs + sp) * NC + oc0;
        float4 r0, r1;
        r0.x = fmaxf(acc[i][0] + bv0.x, 0.f);
        r0.y = fmaxf(acc[i][1] + bv0.y, 0.f);
        r0.z = fmaxf(acc[i][2] + bv0.z, 0.f);
        r0.w = fmaxf(acc[i][3] + bv0.w, 0.f);
        r1.x = fmaxf(acc[i][4] + bv1.x, 0.f);
        r1.y = fmaxf(acc[i][5] + bv1.y, 0.f);
        r1.z = fmaxf(acc[i][6] + bv1.z, 0.f);
        r1.w = fmaxf(acc[i][7] + bv1.w, 0.f);
        *(float4*)&hp[ty * 4]      = r0;
        *(float4*)&hp[ty * 4 + 64] = r1;
    }
}

// ---------------- helpers ----------------
__device__ __forceinline__ unsigned int fdesc(float f) {
    unsigned int u = __float_as_uint(f);
    unsigned int asc = (u & 0x80000000u) ? ~u : (u | 0x80000000u);
    return ~asc;
}
__device__ __forceinline__ void base_anchor(int a, float& y1, float& x1, float& y2, float& x2) {
    int ri = a / 3, si = a % 3;
    double ratio = (ri == 0) ? 0.5 : (ri == 1 ? 1.0 : 2.0);
    double scale = (si == 0) ? 8.0 : (si == 1 ? 16.0 : 32.0);
    double h = 16.0 * scale * sqrt(ratio);
    double w = 16.0 * scale * sqrt(1.0 / ratio);
    y1 = (float)(8.0 - h * 0.5); x1 = (float)(8.0 - w * 0.5);
    y2 = (float)(8.0 + h * 0.5); x2 = (float)(8.0 + w * 0.5);
}

// ---------------- 1x1 heads + softmax + decode + sort-key pack ----------------
__global__ void __launch_bounds__(128) heads_kernel(const float* __restrict__ sw,
                                                    const float* __restrict__ sb,
                                                    const float* __restrict__ lw,
                                                    const float* __restrict__ lb,
                                                    float* __restrict__ out) {
    __shared__ float s_w[128 * 54];
    int b = blockIdx.y;
    int pos = blockIdx.x * 128 + threadIdx.x;

    float acc[54];
#pragma unroll
    for (int o = 0; o < 54; o++) acc[o] = 0.f;

    for (int c0 = 0; c0 < NC; c0 += 128) {
        __syncthreads();
        for (int idx = threadIdx.x; idx < 128 * 54; idx += 128) {
            int o = idx / 128, c = idx % 128;
            float v = (o < 18) ? sw[o * 512 + c0 + c] : lw[(o - 18) * 512 + c0 + c];
            s_w[c * 54 + o] = v;
        }
        __syncthreads();
        const float4* hp4 = (const float4*)(g_h + ((size_t)b * HWs + pos) * NC + c0);
        for (int c4 = 0; c4 < 32; c4++) {
            float4 v = hp4[c4];
            const float* w0 = &s_w[(c4 * 4 + 0) * 54];
            const float* w1 = &s_w[(c4 * 4 + 1) * 54];
            const float* w2 = &s_w[(c4 * 4 + 2) * 54];
            const float* w3 = &s_w[(c4 * 4 + 3) * 54];
#pragma unroll
            for (int o = 0; o < 54; o++) {
                acc[o] = fmaf(v.x, w0[o], acc[o]);
                acc[o] = fmaf(v.y, w1[o], acc[o]);
                acc[o] = fmaf(v.z, w2[o], acc[o]);
                acc[o] = fmaf(v.w, w3[o], acc[o]);
            }
        }
    }
#pragma unroll
    for (int o = 0; o < 18; o++) acc[o] += sb[o];
#pragma unroll
    for (int j = 0; j < 36; j++) acc[18 + j] += lb[j];

    float* os = out + (size_t)(b * HWs + pos) * 18;
#pragma unroll
    for (int o = 0; o < 18; o++) os[o] = acc[o];
    float* ol = out + OFF_LOCS + (size_t)(b * HWs + pos) * 36;
#pragma unroll
    for (int j = 0; j < 36; j++) ol[j] = acc[18 + j];

    int y = pos >> 6, xq = pos & 63;
    float fy = (float)(y * 16), fx = (float)(xq * 16);
#pragma unroll
    for (int a = 0; a < 9; a++) {
        float by1, bx1, by2, bx2;
        base_anchor(a, by1, bx1, by2, bx2);
        float ay1 = fy + by1, ax1 = fx + bx1, ay2 = fy + by2, ax2 = fx + bx2;
        float hA = ay2 - ay1, wA = ax2 - ax1;
        float cy = ay1 + 0.5f * hA, cx = ax1 + 0.5f * wA;
        float dy = acc[18 + 4 * a + 0], dx = acc[18 + 4 * a + 1];
        float dh = acc[18 + 4 * a + 2], dw = acc[18 + 4 * a + 3];
        float cty = dy * hA + cy, ctx = dx * wA + cx;
        float th = expf(dh) * hA, tw = expf(dw) * wA;
        float y1 = cty - 0.5f * th, x1 = ctx - 0.5f * tw;
        float y2 = cty + 0.5f * th, x2 = ctx + 0.5f * tw;
        y1 = fminf(fmaxf(y1, 0.f), 1024.f);
        y2 = fminf(fmaxf(y2, 0.f), 1024.f);
        x1 = fminf(fmaxf(x1, 0.f), 1024.f);
        x2 = fminf(fmaxf(x2, 0.f), 1024.f);
        bool valid = (y2 - y1 >= 16.f) && (x2 - x1 >= 16.f);

        float s0 = acc[2 * a], s1 = acc[2 * a + 1];
        float m = fmaxf(s0, s1);
        float e0 = expf(s0 - m), e1 = expf(s1 - m);
        float fg = e1 / (e0 + e1);
        float skey = valid ? fg : -INFINITY;

        int r = pos * 9 + a;
        size_t ro = ((size_t)b * NA + r) * 4;
        g_rois[ro + 0] = y1; g_rois[ro + 1] = x1;
        g_rois[ro + 2] = y2; g_rois[ro + 3] = x2;
        g_valid[b * NA + r] = valid ? 1 : 0;
        g_keys[(size_t)b * NSORT + r] = ((u64)fdesc(skey) << 32) | (unsigned)r;
    }
}

__global__ void pad_keys_kernel() {
    int gid = blockIdx.x * blockDim.x + threadIdx.x;
    int per = NSORT - NA;
    if (gid >= NB * per) return;
    int b = gid / per, i = NA + gid % per;
    g_keys[(size_t)b * NSORT + i] = ~0ull;
}

// ---------------- bitonic sort ----------------
__global__ void __launch_bounds__(1024) bitonic_local_sort() {
    __shared__ u64 s[4096];
    int base = blockIdx.x * 4096;
#pragma unroll
    for (int m = 0; m < 4; m++) s[threadIdx.x + 1024 * m] = g_keys[base + threadIdx.x + 1024 * m];
    for (int k = 2; k <= 4096; k <<= 1) {
        for (int j = k >> 1; j > 0; j >>= 1) {
            __syncthreads();
#pragma unroll
            for (int m = 0; m < 4; m++) {
                int i = threadIdx.x + 1024 * m;
                int p = i ^ j;
                if (p > i) {
                    int lidx = (base + i) & (NSORT - 1);
                    bool asc = ((lidx & k) == 0);
                    u64 av = s[i], bv = s[p];
                    if (asc ? (av > bv) : (av < bv)) { s[i] = bv; s[p] = av; }
                }
            }
        }
    }
    __syncthreads();
#pragma unroll
    for (int m = 0; m < 4; m++) g_keys[base + threadIdx.x + 1024 * m] = s[threadIdx.x + 1024 * m];
}

__global__ void __launch_bounds__(256) bitonic_global_step(int k, int j) {
    int gid = blockIdx.x * blockDim.x + threadIdx.x;
    int seg = gid >> 16, idx = gid & (NSORT - 1);
    int p = idx ^ j;
    if (p > idx) {
        bool asc = ((idx & k) == 0);
        u64* bptr = g_keys + ((size_t)seg << 16);
        u64 av = bptr[idx], bv = bptr[p];
        if (asc ? (av > bv) : (av < bv)) { bptr[idx] = bv; bptr[p] = av; }
    }
}

__global__ void __launch_bounds__(1024) bitonic_local_merge(int k) {
    __shared__ u64 s[4096];
    int base = blockIdx.x * 4096;
    bool asc = (((base & (NSORT - 1)) & k) == 0);
#pragma unroll
    for (int m = 0; m < 4; m++) s[threadIdx.x + 1024 * m] = g_keys[base + threadIdx.x + 1024 * m];
    for (int j = 2048; j > 0; j >>= 1) {
        __syncthreads();
#pragma unroll
        for (int m = 0; m < 4; m++) {
            int i = threadIdx.x + 1024 * m;
            int p = i ^ j;
            if (p > i) {
                u64 av = s[i], bv = s[p];
                if (asc ? (av > bv) : (av < bv)) { s[i] = bv; s[p] = av; }
            }
        }
    }
    __syncthreads();
#pragma unroll
    for (int m = 0; m < 4; m++) g_keys[base + threadIdx.x + 1024 * m] = s[threadIdx.x + 1024 * m];
}

__global__ void gather_kernel() {
    int gid = blockIdx.x * blockDim.x + threadIdx.x;
    if (gid >= NB * NIN) return;
    int b = gid / NIN, i = gid % NIN;
    u64 key = g_keys[(size_t)b * NSORT + i];
    unsigned r = (unsigned)(key & 0xffffffffu);
    size_t src = ((size_t)b * NA + r) * 4;
    size_t dst = ((size_t)b * NPAD + i) * 4;
    g_rois_s[dst + 0] = g_rois[src + 0];
    g_rois_s[dst + 1] = g_rois[src + 1];
    g_rois_s[dst + 2] = g_rois[src + 2];
    g_rois_s[dst + 3] = g_rois[src + 3];
    g_valid_s[b * NPAD + i] = g_valid[b * NA + r];
}

__global__ void __launch_bounds__(64) mask_kernel() {
    int rb = blockIdx.x, cb = blockIdx.y, b = blockIdx.z;
    if (cb < rb) return;
    __shared__ float4 sj[64];
    int u = threadIdx.x;
    const float4* rs = (const float4*)g_rois_s;
    sj[u] = rs[(size_t)b * NPAD + cb * 64 + u];
    __syncthreads();
    int i = rb * 64 + u;
    if (i >= NIN) return;
    float4 bi = rs[(size_t)b * NPAD + i];
    float ai = (bi.z - bi.x) * (bi.w - bi.y);
    u64 bits = 0;
#pragma unroll 8
    for (int q = 0; q < 64; q++) {
        int jj = cb * 64 + q;
        if (jj > i) {
            float4 bj = sj[q];
            float yy1 = fmaxf(bi.x, bj.x), xx1 = fmaxf(bi.y, bj.y);
            float yy2 = fminf(bi.z, bj.z), xx2 = fminf(bi.w, bj.w);
            float inter = fmaxf(yy2 - yy1, 0.f) * fmaxf(xx2 - xx1, 0.f);
            float aj = (bj.z - bj.x) * (bj.w - bj.y);
            float iou = inter / (ai + aj - inter + 1e-9f);
            if (iou > 0.7f) bits |= (1ull << q);
        }
    }
    g_mask[((size_t)b * NIN + i) * NWRD + cb] = bits;
}

__global__ void __launch_bounds__(32) nms_scan_kernel() {
    int b = blockIdx.x;
    int lane = threadIdx.x;
    const u64* mask = g_mask + (size_t)b * NIN * NWRD;
    const unsigned char* vs = g_valid_s + b * NPAD;
    unsigned char* keep = g_keep + b * NIN;
    int w0 = lane, w1 = lane + 32, w2 = lane + 64;
    bool has2 = (w2 < NWRD);
    u64 r0 = 0, r1 = 0, r2 = 0;
    u64 bufA[8][3], bufB[8][3];
    unsigned char vA[8], vB[8];
#pragma unroll
    for (int t = 0; t < 8; t++) {
        const u64* row = mask + (size_t)t * NWRD;
        bufA[t][0] = row[w0]; bufA[t][1] = row[w1];
        bufA[t][2] = has2 ? row[w2] : 0;
        vA[t] = vs[t];
    }
    for (int base = 0; base < NIN; base += 16) {
#pragma unroll
        for (int t = 0; t < 8; t++) {
            int ri = base + 8 + t;
            if (ri < NIN) {
                const u64* row = mask + (size_t)ri * NWRD;
                bufB[t][0] = row[w0]; bufB[t][1] = row[w1];
                bufB[t][2] = has2 ? row[w2] : 0;
                vB[t] = vs[ri];
            } else { bufB[t][0] = bufB[t][1] = bufB[t][2] = 0; vB[t] = 0; }
        }
#pragma unroll
        for (int t = 0; t < 8; t++) {
            int i = base + t;
            int iw = i >> 6;
            int sel = iw >> 5, owner = iw & 31;
            u64 myw = (sel == 0) ? r0 : ((sel == 1) ? r1 : r2);
            u64 wv = __shfl_sync(0xffffffffu, myw, owner);
            bool alive = vA[t] && !((wv >> (i & 63)) & 1ull);
            if (alive) { r0 |= bufA[t][0]; r1 |= bufA[t][1]; r2 |= bufA[t][2]; }
            if (lane == 0) keep[i] = alive ? 1 : 0;
        }
#pragma unroll
        for (int t = 0; t < 8; t++) {
            int ri = base + 16 + t;
            if (ri < NIN) {
                const u64* row = mask + (size_t)ri * NWRD;
                bufA[t][0] = row[w0]; bufA[t][1] = row[w1];
                bufA[t][2] = has2 ? row[w2] : 0;
                vA[t] = vs[ri];
            } else { bufA[t][0] = bufA[t][1] = bufA[t][2] = 0; vA[t] = 0; }
        }
#pragma unroll
        for (int t = 0; t < 8; t++) {
            int i = base + 8 + t;
            if (i >= NIN) break;
            int iw = i >> 6;
            int sel = iw >> 5, owner = iw & 31;
            u64 myw = (sel == 0) ? r0 : ((sel == 1) ? r1 : r2);
            u64 wv = __shfl_sync(0xffffffffu, myw, owner);
            bool alive = vB[t] && !((wv >> (i & 63)) & 1ull);
            if (alive) { r0 |= bufB[t][0]; r1 |= bufB[t][1]; r2 |= bufB[t][2]; }
            if (lane == 0) keep[i] = alive ? 1 : 0;
        }
    }
}

__global__ void misc_kernel(float* __restrict__ out) {
    int gid = blockIdx.x * blockDim.x + threadIdx.x;
    if (gid < NB * NOUTP * 4) out[OFF_ROIS + gid] = 0.f;
    if (gid < NB * NOUTP) out[OFF_INDS + gid] = (float)(gid / NOUTP);
}

__global__ void anchors_kernel(float* __restrict__ out) {
    int r = blockIdx.x * blockDim.x + threadIdx.x;
    if (r >= NA) return;
    int p = r / 9, a = r % 9;
    int y = p / 64, x = p % 64;
    float by1, bx1, by2, bx2;
    base_anchor(a, by1, bx1, by2, bx2);
    float fy = (float)(y * 16), fx = (float)(x * 16);
    float* o = out + OFF_ANCH + (size_t)r * 4;
    o[0] = fy + by1; o[1] = fx + bx1; o[2] = fy + by2; o[3] = fx + bx2;
}

__global__ void __launch_bounds__(256) finalize_kernel(float* __restrict__ out) {
    int b = blockIdx.x;
    int tid = threadIdx.x;
    __shared__ int ssum[256];
    const unsigned char* keep = g_keep + b * NIN;
    unsigned char kl[24];
    int start = tid * 24;
    int cnt = 0;
#pragma unroll
    for (int t = 0; t < 24; t++) {
        int i = start + t;
        kl[t] = (i < NIN) ? keep[i] : 0;
        cnt += kl[t];
    }
    ssum[tid] = cnt;
    __syncthreads();
    for (int off = 1; off < 256; off <<= 1) {
        int v = (tid >= off) ? ssum[tid - off] : 0;
        __syncthreads();
        ssum[tid] += v;
        __syncthreads();
    }
    int r = ssum[tid] - cnt;
    const float4* rs = (const float4*)g_rois_s;
#pragma unroll
    for (int t = 0; t < 24; t++) {
        if (kl[t]) {
            if (r < NOUTP) {
                int i = start + t;
                float4 bx = rs[(size_t)b * NPAD + i];
                float* o = out + OFF_ROIS + (size_t)(b * NOUTP + r) * 4;
                o[0] = bx.x; o[1] = bx.y; o[2] = bx.z; o[3] = bx.w;
            }
            r++;
        }
    }
}

// ---------------- launch ----------------
extern "C" void kernel_launch(void* const* d_in, const int* in_sizes, int n_in,
                              void* d_out, int out_size) {
    const float* x       = (const float*)d_in[0];
    const float* conv_w  = (const float*)d_in[1];
    const float* conv_b  = (const float*)d_in[2];
    const float* score_w = (const float*)d_in[3];
    const float* score_b = (const float*)d_in[4];
    const float* loc_w   = (const float*)d_in[5];
    const float* loc_b   = (const float*)d_in[6];
    float* out = (float*)d_out;

    conv_ffma_kernel<<<dim3(32, 4, NB), 256>>>(x, conv_w, conv_b);
    heads_kernel<<<dim3(32, NB), 128>>>(score_w, score_b, loc_w, loc_b, out);
    pad_keys_kernel<<<(NB * (NSORT - NA) + 255) / 256, 256>>>();

    bitonic_local_sort<<<NB * NSORT / 4096, 1024>>>();
    for (int k = 8192; k <= NSORT; k <<= 1) {
        for (int j = k >> 1; j >= 4096; j >>= 1)
            bitonic_global_step<<<NB * NSORT / 256, 256>>>(k, j);
        bitonic_local_merge<<<NB * NSORT / 4096, 1024>>>(k);
    }

    gather_kernel<<<(NB * NIN + 255) / 256, 256>>>();
    mask_kernel<<<dim3(NWRD, NWRD, NB), 64>>>();
    nms_scan_kernel<<<NB, 32>>>();
    misc_kernel<<<(NB * NOUTP * 4 + 255) / 256, 256>>>(out);
    anchors_kernel<<<(NA + 255) / 256, 256>>>(out);
    finalize_kernel<<<NB, 256>>>(out);
}

// round 10
// speedup vs baseline: 2.0371x; 1.2856x over previous
#include <cuda_runtime.h>
#include <math.h>
#include <stdint.h>

#define NB   4
#define NC   512
#define HWs  4096
#define NA   36864
#define NSORT 65536
#define NIN  6000
#define NWRD 94
#define NPAD 6016
#define NOUTP 300
#define KTOT 4608
#define NCHUNK 288     // K chunks of 16

#define OFF_LOCS 294912
#define OFF_ROIS 884736
#define OFF_INDS 889536
#define OFF_ANCH 890736

typedef unsigned long long u64;

// ---------------- scratch ----------------
__device__ float g_h[(size_t)NB * HWs * NC];   // layout [b][sp][oc]
__device__ float g_rois[(size_t)NB * NA * 4];
__device__ unsigned char g_valid[NB * NA];
__device__ u64 g_keys[NB * NSORT];
__device__ float g_rois_s[NB * NPAD * 4];
__device__ unsigned char g_valid_s[NB * NPAD];
__device__ u64 g_mask[(size_t)NB * NIN * NWRD];
__device__ unsigned char g_keep[NB * NIN];

// ---------------- FFMA implicit-GEMM conv (128x128 tile, 8x8 micro-tile) ----------------
// grid (32 sp-tiles, 4 oc-tiles, 4 batch), 256 threads.
__global__ void __launch_bounds__(256, 2) conv_ffma_kernel(const float* __restrict__ x,
                                                           const float* __restrict__ w,
                                                           const float* __restrict__ bias) {
    __shared__ float sA[16][128];
    __shared__ float sW[16][128];

    int tid = threadIdx.x;
    int b = blockIdx.z, spt = blockIdx.x, ocg = blockIdx.y;
    int sp0 = spt * 128, oc0 = ocg * 128;
    int tx = tid & 15, ty = tid >> 4;

    float acc[8][8];
#pragma unroll
    for (int i = 0; i < 8; i++)
#pragma unroll
        for (int j = 0; j < 8; j++) acc[i][j] = 0.f;

    const float* xb = x + (size_t)b * NC * HWs;

    int spl = tid & 127;
    int j0 = tid >> 7;
    int y = (sp0 + spl) >> 6, xq = (sp0 + spl) & 63;
    int ocl = tid >> 1;
    int kl0 = (tid & 1) * 8;

    float vA[8];
    float4 w0r, w1r;

#pragma unroll
    for (int i = 0; i < 8; i++) {
        int kg = j0 + 2 * i;
        int ic = kg / 9, t = kg - ic * 9;
        int yy = y + t / 3 - 1, xx = xq + t % 3 - 1;
        bool ok = ((unsigned)yy < 64u) & ((unsigned)xx < 64u);
        vA[i] = ok ? __ldg(xb + (size_t)ic * HWs + yy * 64 + xx) : 0.f;
    }
    {
        const float4* pw = (const float4*)(w + (size_t)(oc0 + ocl) * KTOT + kl0);
        w0r = pw[0]; w1r = pw[1];
    }

    for (int c = 0; c < NCHUNK; c++) {
#pragma unroll
        for (int i = 0; i < 8; i++) sA[j0 + 2 * i][spl] = vA[i];
        sW[kl0 + 0][ocl] = w0r.x; sW[kl0 + 1][ocl] = w0r.y;
        sW[kl0 + 2][ocl] = w0r.z; sW[kl0 + 3][ocl] = w0r.w;
        sW[kl0 + 4][ocl] = w1r.x; sW[kl0 + 5][ocl] = w1r.y;
        sW[kl0 + 6][ocl] = w1r.z; sW[kl0 + 7][ocl] = w1r.w;
        __syncthreads();

        if (c + 1 < NCHUNK) {
            int cn = c + 1;
#pragma unroll
            for (int i = 0; i < 8; i++) {
                int kg = cn * 16 + j0 + 2 * i;
                int ic = kg / 9, t = kg - ic * 9;
                int yy = y + t / 3 - 1, xx = xq + t % 3 - 1;
                bool ok = ((unsigned)yy < 64u) & ((unsigned)xx < 64u);
                vA[i] = ok ? __ldg(xb + (size_t)ic * HWs + yy * 64 + xx) : 0.f;
            }
            const float4* pw = (const float4*)(w + (size_t)(oc0 + ocl) * KTOT + cn * 16 + kl0);
            w0r = pw[0]; w1r = pw[1];
        }

#pragma unroll
        for (int k = 0; k < 16; k++) {
            float4 a0 = *(const float4*)&sA[k][tx * 4];
            float4 a1 = *(const float4*)&sA[k][tx * 4 + 64];
            float4 b0 = *(const float4*)&sW[k][ty * 4];
            float4 b1 = *(const float4*)&sW[k][ty * 4 + 64];
            float av[8] = {a0.x, a0.y, a0.z, a0.w, a1.x, a1.y, a1.z, a1.w};
            float bv[8] = {b0.x, b0.y, b0.z, b0.w, b1.x, b1.y, b1.z, b1.w};
#pragma unroll
            for (int i = 0; i < 8; i++)
#pragma unroll
                for (int j = 0; j < 8; j++)
                    acc[i][j] = fmaf(av[i], bv[j], acc[i][j]);
        }
        __syncthreads();
    }

    float4 bv0 = *(const float4*)&bias[oc0 + ty * 4];
    float4 bv1 = *(const float4*)&bias[oc0 + ty * 4 + 64];
#pragma unroll
    for (int i = 0; i < 8; i++) {
        int sp = sp0 + ((i < 4) ? (tx * 4 + i) : (64 + tx * 4 + i - 4));
        float* hp = g_h + ((size_t)b * HWs + sp) * NC + oc0;
        float4 r0, r1;
        r0.x = fmaxf(acc[i][0] + bv0.x, 0.f);
        r0.y = fmaxf(acc[i][1] + bv0.y, 0.f);
        r0.z = fmaxf(acc[i][2] + bv0.z, 0.f);
        r0.w = fmaxf(acc[i][3] + bv0.w, 0.f);
        r1.x = fmaxf(acc[i][4] + bv1.x, 0.f);
        r1.y = fmaxf(acc[i][5] + bv1.y, 0.f);
        r1.z = fmaxf(acc[i][6] + bv1.z, 0.f);
        r1.w = fmaxf(acc[i][7] + bv1.w, 0.f);
        *(float4*)&hp[ty * 4]      = r0;
        *(float4*)&hp[ty * 4 + 64] = r1;
    }
}

// ---------------- helpers ----------------
__device__ __forceinline__ unsigned int fdesc(float f) {
    unsigned int u = __float_as_uint(f);
    unsigned int asc = (u & 0x80000000u) ? ~u : (u | 0x80000000u);
    return ~asc;
}
__device__ __forceinline__ void base_anchor(int a, float& y1, float& x1, float& y2, float& x2) {
    int ri = a / 3, si = a % 3;
    double ratio = (ri == 0) ? 0.5 : (ri == 1 ? 1.0 : 2.0);
    double scale = (si == 0) ? 8.0 : (si == 1 ? 16.0 : 32.0);
    double h = 16.0 * scale * sqrt(ratio);
    double w = 16.0 * scale * sqrt(1.0 / ratio);
    y1 = (float)(8.0 - h * 0.5); x1 = (float)(8.0 - w * 0.5);
    y2 = (float)(8.0 + h * 0.5); x2 = (float)(8.0 + w * 0.5);
}

// ---------------- 1x1 heads: 2-way channel-split (2x warp parallelism) ----------------
// grid (64, NB), 128 threads: threads [0,64) = half 0 (c 0..255), [64,128) = half 1 (c 256..511).
__global__ void __launch_bounds__(128) heads_kernel(const float* __restrict__ sw,
                                                    const float* __restrict__ sb,
                                                    const float* __restrict__ lw,
                                                    const float* __restrict__ lb,
                                                    float* __restrict__ out) {
    __shared__ float s_w[2][64][54];
    __shared__ float s_red[64][56];
    int b = blockIdx.y;
    int tid = threadIdx.x;
    int p = tid & 63, half = tid >> 6;
    int pos = blockIdx.x * 64 + p;

    float acc[54];
#pragma unroll
    for (int o = 0; o < 54; o++) acc[o] = 0.f;

    for (int ch = 0; ch < 4; ch++) {
        int c0 = half * 256 + ch * 64;
        __syncthreads();
#pragma unroll
        for (int o = 0; o < 54; o++) {
            int c = p;
            float v = (o < 18) ? sw[o * 512 + c0 + c] : lw[(o - 18) * 512 + c0 + c];
            s_w[half][c][o] = v;
        }
        __syncthreads();
        const float4* hp4 = (const float4*)(g_h + ((size_t)b * HWs + pos) * NC + c0);
        for (int c4 = 0; c4 < 16; c4++) {
            float4 v = hp4[c4];
            const float* w0 = &s_w[half][c4 * 4 + 0][0];
            const float* w1 = &s_w[half][c4 * 4 + 1][0];
            const float* w2 = &s_w[half][c4 * 4 + 2][0];
            const float* w3 = &s_w[half][c4 * 4 + 3][0];
#pragma unroll
            for (int o = 0; o < 54; o++) {
                acc[o] = fmaf(v.x, w0[o], acc[o]);
                acc[o] = fmaf(v.y, w1[o], acc[o]);
                acc[o] = fmaf(v.z, w2[o], acc[o]);
                acc[o] = fmaf(v.w, w3[o], acc[o]);
            }
        }
    }

    // combine halves
    if (half == 1) {
#pragma unroll
        for (int o = 0; o < 54; o++) s_red[p][o] = acc[o];
    }
    __syncthreads();
    if (half == 1) return;
#pragma unroll
    for (int o = 0; o < 54; o++) acc[o] += s_red[p][o];

#pragma unroll
    for (int o = 0; o < 18; o++) acc[o] += sb[o];
#pragma unroll
    for (int j = 0; j < 36; j++) acc[18 + j] += lb[j];

    float* os = out + (size_t)(b * HWs + pos) * 18;
#pragma unroll
    for (int o = 0; o < 18; o++) os[o] = acc[o];
    float* ol = out + OFF_LOCS + (size_t)(b * HWs + pos) * 36;
#pragma unroll
    for (int j = 0; j < 36; j++) ol[j] = acc[18 + j];

    int y = pos >> 6, xq = pos & 63;
    float fy = (float)(y * 16), fx = (float)(xq * 16);
#pragma unroll
    for (int a = 0; a < 9; a++) {
        float by1, bx1, by2, bx2;
        base_anchor(a, by1, bx1, by2, bx2);
        float ay1 = fy + by1, ax1 = fx + bx1, ay2 = fy + by2, ax2 = fx + bx2;
        float hA = ay2 - ay1, wA = ax2 - ax1;
        float cy = ay1 + 0.5f * hA, cx = ax1 + 0.5f * wA;
        float dy = acc[18 + 4 * a + 0], dx = acc[18 + 4 * a + 1];
        float dh = acc[18 + 4 * a + 2], dw = acc[18 + 4 * a + 3];
        float cty = dy * hA + cy, ctx = dx * wA + cx;
        float th = expf(dh) * hA, tw = expf(dw) * wA;
        float y1 = cty - 0.5f * th, x1 = ctx - 0.5f * tw;
        float y2 = cty + 0.5f * th, x2 = ctx + 0.5f * tw;
        y1 = fminf(fmaxf(y1, 0.f), 1024.f);
        y2 = fminf(fmaxf(y2, 0.f), 1024.f);
        x1 = fminf(fmaxf(x1, 0.f), 1024.f);
        x2 = fminf(fmaxf(x2, 0.f), 1024.f);
        bool valid = (y2 - y1 >= 16.f) && (x2 - x1 >= 16.f);

        float s0 = acc[2 * a], s1 = acc[2 * a + 1];
        float m = fmaxf(s0, s1);
        float e0 = expf(s0 - m), e1 = expf(s1 - m);
        float fg = e1 / (e0 + e1);
        float skey = valid ? fg : -INFINITY;

        int r = pos * 9 + a;
        size_t ro = ((size_t)b * NA + r) * 4;
        g_rois[ro + 0] = y1; g_rois[ro + 1] = x1;
        g_rois[ro + 2] = y2; g_rois[ro + 3] = x2;
        g_valid[b * NA + r] = valid ? 1 : 0;
        g_keys[(size_t)b * NSORT + r] = ((u64)fdesc(skey) << 32) | (unsigned)r;
    }
}

// ---------------- fused aux: pad keys + anchors + rois-zero + indices + keep-zero ----------------
__global__ void aux_kernel(float* __restrict__ out) {
    int gid = blockIdx.x * blockDim.x + threadIdx.x;
    int per = NSORT - NA;  // 28672
    if (gid < NB * per) {
        int b = gid / per, i = NA + gid % per;
        g_keys[(size_t)b * NSORT + i] = ~0ull;
    }
    if (gid < NA) {
        int p = gid / 9, a = gid % 9;
        int y = p / 64, x = p % 64;
        float by1, bx1, by2, bx2;
        base_anchor(a, by1, bx1, by2, bx2);
        float fy = (float)(y * 16), fx = (float)(x * 16);
        float* o = out + OFF_ANCH + (size_t)gid * 4;
        o[0] = fy + by1; o[1] = fx + bx1; o[2] = fy + by2; o[3] = fx + bx2;
    }
    if (gid < NB * NOUTP * 4) out[OFF_ROIS + gid] = 0.f;
    if (gid < NB * NOUTP) out[OFF_INDS + gid] = (float)(gid / NOUTP);
    if (gid < NB * NIN) g_keep[gid] = 0;
}

// ---------------- bitonic sort ----------------
__global__ void __launch_bounds__(1024) bitonic_local_sort() {
    __shared__ u64 s[4096];
    int base = blockIdx.x * 4096;
#pragma unroll
    for (int m = 0; m < 4; m++) s[threadIdx.x + 1024 * m] = g_keys[base + threadIdx.x + 1024 * m];
    for (int k = 2; k <= 4096; k <<= 1) {
        for (int j = k >> 1; j > 0; j >>= 1) {
            __syncthreads();
#pragma unroll
            for (int m = 0; m < 4; m++) {
                int i = threadIdx.x + 1024 * m;
                int p = i ^ j;
                if (p > i) {
                    int lidx = (base + i) & (NSORT - 1);
                    bool asc = ((lidx & k) == 0);
                    u64 av = s[i], bv = s[p];
                    if (asc ? (av > bv) : (av < bv)) { s[i] = bv; s[p] = av; }
                }
            }
        }
    }
    __syncthreads();
#pragma unroll
    for (int m = 0; m < 4; m++) g_keys[base + threadIdx.x + 1024 * m] = s[threadIdx.x + 1024 * m];
}

__global__ void __launch_bounds__(256) bitonic_global_step(int k, int j) {
    int gid = blockIdx.x * blockDim.x + threadIdx.x;
    int seg = gid >> 16, idx = gid & (NSORT - 1);
    int p = idx ^ j;
    if (p > idx) {
        bool asc = ((idx & k) == 0);
        u64* bptr = g_keys + ((size_t)seg << 16);
        u64 av = bptr[idx], bv = bptr[p];
        if (asc ? (av > bv) : (av < bv)) { bptr[idx] = bv; bptr[p] = av; }
    }
}

__global__ void __launch_bounds__(1024) bitonic_local_merge(int k) {
    __shared__ u64 s[4096];
    int base = blockIdx.x * 4096;
    bool asc = (((base & (NSORT - 1)) & k) == 0);
#pragma unroll
    for (int m = 0; m < 4; m++) s[threadIdx.x + 1024 * m] = g_keys[base + threadIdx.x + 1024 * m];
    for (int j = 2048; j > 0; j >>= 1) {
        __syncthreads();
#pragma unroll
        for (int m = 0; m < 4; m++) {
            int i = threadIdx.x + 1024 * m;
            int p = i ^ j;
            if (p > i) {
                u64 av = s[i], bv = s[p];
                if (asc ? (av > bv) : (av < bv)) { s[i] = bv; s[p] = av; }
            }
        }
    }
    __syncthreads();
#pragma unroll
    for (int m = 0; m < 4; m++) g_keys[base + threadIdx.x + 1024 * m] = s[threadIdx.x + 1024 * m];
}

__global__ void gather_kernel() {
    int gid = blockIdx.x * blockDim.x + threadIdx.x;
    if (gid >= NB * NIN) return;
    int b = gid / NIN, i = gid % NIN;
    u64 key = g_keys[(size_t)b * NSORT + i];
    unsigned r = (unsigned)(key & 0xffffffffu);
    size_t src = ((size_t)b * NA + r) * 4;
    size_t dst = ((size_t)b * NPAD + i) * 4;
    g_rois_s[dst + 0] = g_rois[src + 0];
    g_rois_s[dst + 1] = g_rois[src + 1];
    g_rois_s[dst + 2] = g_rois[src + 2];
    g_rois_s[dst + 3] = g_rois[src + 3];
    g_valid_s[b * NPAD + i] = g_valid[b * NA + r];
}

__global__ void __launch_bounds__(64) mask_kernel() {
    int rb = blockIdx.x, cb = blockIdx.y, b = blockIdx.z;
    if (cb < rb) return;
    __shared__ float4 sj[64];
    int u = threadIdx.x;
    const float4* rs = (const float4*)g_rois_s;
    sj[u] = rs[(size_t)b * NPAD + cb * 64 + u];
    __syncthreads();
    int i = rb * 64 + u;
    if (i >= NIN) return;
    float4 bi = rs[(size_t)b * NPAD + i];
    float ai = (bi.z - bi.x) * (bi.w - bi.y);
    u64 bits = 0;
#pragma unroll 8
    for (int q = 0; q < 64; q++) {
        int jj = cb * 64 + q;
        if (jj > i) {
            float4 bj = sj[q];
            float yy1 = fmaxf(bi.x, bj.x), xx1 = fmaxf(bi.y, bj.y);
            float yy2 = fminf(bi.z, bj.z), xx2 = fminf(bi.w, bj.w);
            float inter = fmaxf(yy2 - yy1, 0.f) * fmaxf(xx2 - xx1, 0.f);
            float aj = (bj.z - bj.x) * (bj.w - bj.y);
            float iou = inter / (ai + aj - inter + 1e-9f);
            if (iou > 0.7f) bits |= (1ull << q);
        }
    }
    g_mask[((size_t)b * NIN + i) * NWRD + cb] = bits;
}

// ---------------- greedy NMS scan with early exit at 300 keeps ----------------
__global__ void __launch_bounds__(32) nms_scan_kernel() {
    int b = blockIdx.x;
    int lane = threadIdx.x;
    const u64* mask = g_mask + (size_t)b * NIN * NWRD;
    const unsigned char* vs = g_valid_s + b * NPAD;
    unsigned char* keep = g_keep + b * NIN;
    int w0 = lane, w1 = lane + 32, w2 = lane + 64;
    bool has2 = (w2 < NWRD);
    u64 r0 = 0, r1 = 0, r2 = 0;
    u64 bufA[8][3], bufB[8][3];
    unsigned char vA[8], vB[8];
    int kept = 0;
#pragma unroll
    for (int t = 0; t < 8; t++) {
        const u64* row = mask + (size_t)t * NWRD;
        bufA[t][0] = row[w0]; bufA[t][1] = row[w1];
        bufA[t][2] = has2 ? row[w2] : 0;
        vA[t] = vs[t];
    }
    for (int base = 0; base < NIN; base += 16) {
#pragma unroll
        for (int t = 0; t < 8; t++) {
            int ri = base + 8 + t;
            if (ri < NIN) {
                const u64* row = mask + (size_t)ri * NWRD;
                bufB[t][0] = row[w0]; bufB[t][1] = row[w1];
                bufB[t][2] = has2 ? row[w2] : 0;
                vB[t] = vs[ri];
            } else { bufB[t][0] = bufB[t][1] = bufB[t][2] = 0; vB[t] = 0; }
        }
#pragma unroll
        for (int t = 0; t < 8; t++) {
            int i = base + t;
            int iw = i >> 6;
            int sel = iw >> 5, owner = iw & 31;
            u64 myw = (sel == 0) ? r0 : ((sel == 1) ? r1 : r2);
            u64 wv = __shfl_sync(0xffffffffu, myw, owner);
            bool alive = vA[t] && !((wv >> (i & 63)) & 1ull);
            if (alive) {
                r0 |= bufA[t][0]; r1 |= bufA[t][1]; r2 |= bufA[t][2];
                kept++;
                if (lane == 0) keep[i] = 1;
            }
        }
        if (kept >= NOUTP) return;
#pragma unroll
        for (int t = 0; t < 8; t++) {
            int ri = base + 16 + t;
            if (ri < NIN) {
                const u64* row = mask + (size_t)ri * NWRD;
                bufA[t][0] = row[w0]; bufA[t][1] = row[w1];
                bufA[t][2] = has2 ? row[w2] : 0;
                vA[t] = vs[ri];
            } else { bufA[t][0] = bufA[t][1] = bufA[t][2] = 0; vA[t] = 0; }
        }
#pragma unroll
        for (int t = 0; t < 8; t++) {
            int i = base + 8 + t;
            if (i >= NIN) break;
            int iw = i >> 6;
            int sel = iw >> 5, owner = iw & 31;
            u64 myw = (sel == 0) ? r0 : ((sel == 1) ? r1 : r2);
            u64 wv = __shfl_sync(0xffffffffu, myw, owner);
            bool alive = vB[t] && !((wv >> (i & 63)) & 1ull);
            if (alive) {
                r0 |= bufB[t][0]; r1 |= bufB[t][1]; r2 |= bufB[t][2];
                kept++;
                if (lane == 0) keep[i] = 1;
            }
        }
        if (kept >= NOUTP) return;
    }
}

__global__ void __launch_bounds__(256) finalize_kernel(float* __restrict__ out) {
    int b = blockIdx.x;
    int tid = threadIdx.x;
    __shared__ int ssum[256];
    const unsigned char* keep = g_keep + b * NIN;
    unsigned char kl[24];
    int start = tid * 24;
    int cnt = 0;
#pragma unroll
    for (int t = 0; t < 24; t++) {
        int i = start + t;
        kl[t] = (i < NIN) ? keep[i] : 0;
        cnt += kl[t];
    }
    ssum[tid] = cnt;
    __syncthreads();
    for (int off = 1; off < 256; off <<= 1) {
        int v = (tid >= off) ? ssum[tid - off] : 0;
        __syncthreads();
        ssum[tid] += v;
        __syncthreads();
    }
    int r = ssum[tid] - cnt;
    const float4* rs = (const float4*)g_rois_s;
#pragma unroll
    for (int t = 0; t < 24; t++) {
        if (kl[t]) {
            if (r < NOUTP) {
                int i = start + t;
                float4 bx = rs[(size_t)b * NPAD + i];
                float* o = out + OFF_ROIS + (size_t)(b * NOUTP + r) * 4;
                o[0] = bx.x; o[1] = bx.y; o[2] = bx.z; o[3] = bx.w;
            }
            r++;
        }
    }
}

// ---------------- launch ----------------
extern "C" void kernel_launch(void* const* d_in, const int* in_sizes, int n_in,
                              void* d_out, int out_size) {
    const float* x       = (const float*)d_in[0];
    const float* conv_w  = (const float*)d_in[1];
    const float* conv_b  = (const float*)d_in[2];
    const float* score_w = (const float*)d_in[3];
    const float* score_b = (const float*)d_in[4];
    const float* loc_w   = (const float*)d_in[5];
    const float* loc_b   = (const float*)d_in[6];
    float* out = (float*)d_out;

    conv_ffma_kernel<<<dim3(32, 4, NB), 256>>>(x, conv_w, conv_b);
    heads_kernel<<<dim3(64, NB), 128>>>(score_w, score_b, loc_w, loc_b, out);
    aux_kernel<<<448, 256>>>(out);

    bitonic_local_sort<<<NB * NSORT / 4096, 1024>>>();
    for (int k = 8192; k <= NSORT; k <<= 1) {
        for (int j = k >> 1; j >= 4096; j >>= 1)
            bitonic_global_step<<<NB * NSORT / 256, 256>>>(k, j);
        bitonic_local_merge<<<NB * NSORT / 4096, 1024>>>(k);
    }

    gather_kernel<<<(NB * NIN + 255) / 256, 256>>>();
    mask_kernel<<<dim3(NWRD, NWRD, NB), 64>>>();
    nms_scan_kernel<<<NB, 32>>>();
    finalize_kernel<<<NB, 256>>>(out);
}

// round 11
// speedup vs baseline: 4.2742x; 2.0982x over previous
#include <cuda_runtime.h>
#include <math.h>
#include <stdint.h>

#define NB   4
#define NC   512
#define HWs  4096
#define NA   36864
#define NSORT 65536
#define NIN  6000
#define NWRD 94
#define NPAD 6016
#define NOUTP 300
#define NTIL 1024      // 32x32 winograd tiles per image
#define KGEMM 512      // ic

#define OFF_LOCS 294912
#define OFF_ROIS 884736
#define OFF_INDS 889536
#define OFF_ANCH 890736

typedef unsigned long long u64;

// ---------------- scratch ----------------
__device__ float g_h[(size_t)NB * HWs * NC];            // [b][sp][oc]
__device__ float g_U[(size_t)16 * NC * NC];             // [e][oc][ic]
__device__ float g_V[(size_t)NB * 16 * NC * NTIL];      // [b*16+e][ic][tile]
__device__ float g_M[(size_t)NB * 16 * NTIL * NC];      // [b*16+e][tile][oc]
__device__ float g_rois[(size_t)NB * NA * 4];
__device__ unsigned char g_valid[NB * NA];
__device__ u64 g_keys[NB * NSORT];
__device__ float g_rois_s[NB * NPAD * 4];
__device__ unsigned char g_valid_s[NB * NPAD];
__device__ u64 g_mask[(size_t)NB * NIN * NWRD];
__device__ unsigned char g_keep[NB * NIN];

// ---------------- winograd filter transform: U = G g G^T ----------------
__global__ void filter_transform_kernel(const float* __restrict__ w) {
    int gid = blockIdx.x * blockDim.x + threadIdx.x;
    if (gid >= NC * NC) return;
    int ic = gid & 511, oc = gid >> 9;
    float g[3][3];
#pragma unroll
    for (int r = 0; r < 3; r++)
#pragma unroll
        for (int c = 0; c < 3; c++)
            g[r][c] = w[(((size_t)oc * NC + ic) * 3 + r) * 3 + c];
    float u[4][3];
#pragma unroll
    for (int c = 0; c < 3; c++) {
        u[0][c] = g[0][c];
        u[1][c] = 0.5f * (g[0][c] + g[1][c] + g[2][c]);
        u[2][c] = 0.5f * (g[0][c] - g[1][c] + g[2][c]);
        u[3][c] = g[2][c];
    }
#pragma unroll
    for (int r = 0; r < 4; r++) {
        float U0 = u[r][0];
        float U1 = 0.5f * (u[r][0] + u[r][1] + u[r][2]);
        float U2 = 0.5f * (u[r][0] - u[r][1] + u[r][2]);
        float U3 = u[r][2];
        g_U[((size_t)(r * 4 + 0) * NC + oc) * NC + ic] = U0;
        g_U[((size_t)(r * 4 + 1) * NC + oc) * NC + ic] = U1;
        g_U[((size_t)(r * 4 + 2) * NC + oc) * NC + ic] = U2;
        g_U[((size_t)(r * 4 + 3) * NC + oc) * NC + ic] = U3;
    }
}

// ---------------- winograd input transform: V = B^T d B ----------------
__global__ void input_transform_kernel(const float* __restrict__ x) {
    int gid = blockIdx.x * blockDim.x + threadIdx.x;
    if (gid >= NB * NC * NTIL) return;
    int tile = gid & 1023;
    int ic = (gid >> 10) & 511;
    int b = gid >> 19;
    int ty = tile >> 5, tx = tile & 31;
    int y0 = 2 * ty - 1, x0 = 2 * tx - 1;
    const float* xp = x + ((size_t)b * NC + ic) * HWs;
    float d[4][4];
#pragma unroll
    for (int r = 0; r < 4; r++)
#pragma unroll
        for (int c = 0; c < 4; c++) {
            int yy = y0 + r, xx = x0 + c;
            bool ok = ((unsigned)yy < 64u) & ((unsigned)xx < 64u);
            d[r][c] = ok ? xp[yy * 64 + xx] : 0.f;
        }
    float z[4][4];
#pragma unroll
    for (int c = 0; c < 4; c++) {
        z[0][c] = d[0][c] - d[2][c];
        z[1][c] = d[1][c] + d[2][c];
        z[2][c] = d[2][c] - d[1][c];
        z[3][c] = d[1][c] - d[3][c];
    }
    float* Vb = g_V + (size_t)b * 16 * NC * NTIL;
#pragma unroll
    for (int r = 0; r < 4; r++) {
        float v0 = z[r][0] - z[r][2];
        float v1 = z[r][1] + z[r][2];
        float v2 = z[r][2] - z[r][1];
        float v3 = z[r][1] - z[r][3];
        Vb[((size_t)(r * 4 + 0) * NC + ic) * NTIL + tile] = v0;
        Vb[((size_t)(r * 4 + 1) * NC + ic) * NTIL + tile] = v1;
        Vb[((size_t)(r * 4 + 2) * NC + ic) * NTIL + tile] = v2;
        Vb[((size_t)(r * 4 + 3) * NC + ic) * NTIL + tile] = v3;
    }
}

// ---------------- winograd GEMM: M[be][tile][oc] = V[be][ic][tile]^T x U[e][oc][ic]^T ----------------
// grid (8 tile-tiles, 4 oc-tiles, 64 = b*16+e), 256 threads, 128x128x512.
__global__ void __launch_bounds__(256, 2) wino_gemm_kernel() {
    __shared__ float sA[16][128];
    __shared__ float sW[16][128];

    int tid = threadIdx.x;
    int be = blockIdx.z;
    int e = be & 15;
    int spt = blockIdx.x, ocg = blockIdx.y;
    int sp0 = spt * 128, oc0 = ocg * 128;
    int tx = tid & 15, ty = tid >> 4;

    float acc[8][8];
#pragma unroll
    for (int i = 0; i < 8; i++)
#pragma unroll
        for (int j = 0; j < 8; j++) acc[i][j] = 0.f;

    const float* Vb = g_V + (size_t)be * NC * NTIL;
    const float* Ue = g_U + (size_t)e * NC * NC;

    int spl = tid & 127;
    int j0 = tid >> 7;
    int ocl = tid >> 1;
    int kl0 = (tid & 1) * 8;

    float vA[8];
    float4 w0r, w1r;

#pragma unroll
    for (int i = 0; i < 8; i++)
        vA[i] = Vb[(size_t)(j0 + 2 * i) * NTIL + sp0 + spl];
    {
        const float4* pw = (const float4*)(Ue + (size_t)(oc0 + ocl) * NC + kl0);
        w0r = pw[0]; w1r = pw[1];
    }

    for (int c = 0; c < 32; c++) {
#pragma unroll
        for (int i = 0; i < 8; i++) sA[j0 + 2 * i][spl] = vA[i];
        sW[kl0 + 0][ocl] = w0r.x; sW[kl0 + 1][ocl] = w0r.y;
        sW[kl0 + 2][ocl] = w0r.z; sW[kl0 + 3][ocl] = w0r.w;
        sW[kl0 + 4][ocl] = w1r.x; sW[kl0 + 5][ocl] = w1r.y;
        sW[kl0 + 6][ocl] = w1r.z; sW[kl0 + 7][ocl] = w1r.w;
        __syncthreads();

        if (c + 1 < 32) {
            int k0 = (c + 1) * 16;
#pragma unroll
            for (int i = 0; i < 8; i++)
                vA[i] = Vb[(size_t)(k0 + j0 + 2 * i) * NTIL + sp0 + spl];
            const float4* pw = (const float4*)(Ue + (size_t)(oc0 + ocl) * NC + k0 + kl0);
            w0r = pw[0]; w1r = pw[1];
        }

#pragma unroll
        for (int k = 0; k < 16; k++) {
            float4 a0 = *(const float4*)&sA[k][tx * 4];
            float4 a1 = *(const float4*)&sA[k][tx * 4 + 64];
            float4 b0 = *(const float4*)&sW[k][ty * 4];
            float4 b1 = *(const float4*)&sW[k][ty * 4 + 64];
            float av[8] = {a0.x, a0.y, a0.z, a0.w, a1.x, a1.y, a1.z, a1.w};
            float bv[8] = {b0.x, b0.y, b0.z, b0.w, b1.x, b1.y, b1.z, b1.w};
#pragma unroll
            for (int i = 0; i < 8; i++)
#pragma unroll
                for (int j = 0; j < 8; j++)
                    acc[i][j] = fmaf(av[i], bv[j], acc[i][j]);
        }
        __syncthreads();
    }

    // epilogue: M[be][tile][oc], oc contiguous
    float* Mb = g_M + (size_t)be * NTIL * NC;
#pragma unroll
    for (int i = 0; i < 8; i++) {
        int sp = sp0 + ((i < 4) ? (tx * 4 + i) : (64 + tx * 4 + i - 4));
        float* mp = Mb + (size_t)sp * NC + oc0;
        float4 r0 = make_float4(acc[i][0], acc[i][1], acc[i][2], acc[i][3]);
        float4 r1 = make_float4(acc[i][4], acc[i][5], acc[i][6], acc[i][7]);
        *(float4*)&mp[ty * 4]      = r0;
        *(float4*)&mp[ty * 4 + 64] = r1;
    }
}

// ---------------- winograd output transform: Y = A^T M A, + bias + relu ----------------
__global__ void output_transform_kernel(const float* __restrict__ bias) {
    int gid = blockIdx.x * blockDim.x + threadIdx.x;
    if (gid >= NB * NTIL * NC) return;
    int oc = gid & 511;
    int tile = (gid >> 9) & 1023;
    int b = gid >> 19;
    const float* Mb = g_M + (size_t)b * 16 * NTIL * NC;
    float m[4][4];
#pragma unroll
    for (int r = 0; r < 4; r++)
#pragma unroll
        for (int c = 0; c < 4; c++)
            m[r][c] = Mb[((size_t)(r * 4 + c) * NTIL + tile) * NC + oc];
    float z0[4], z1[4];
#pragma unroll
    for (int c = 0; c < 4; c++) {
        z0[c] = m[0][c] + m[1][c] + m[2][c];
        z1[c] = m[1][c] - m[2][c] - m[3][c];
    }
    float bv = bias[oc];
    float y00 = fmaxf(z0[0] + z0[1] + z0[2] + bv, 0.f);
    float y01 = fmaxf(z0[1] - z0[2] - z0[3] + bv, 0.f);
    float y10 = fmaxf(z1[0] + z1[1] + z1[2] + bv, 0.f);
    float y11 = fmaxf(z1[1] - z1[2] - z1[3] + bv, 0.f);
    int ty = tile >> 5, tx = tile & 31;
    int yb = 2 * ty, xb = 2 * tx;
    float* hp = g_h + (size_t)b * HWs * NC;
    hp[(size_t)(yb * 64 + xb) * NC + oc] = y00;
    hp[(size_t)(yb * 64 + xb + 1) * NC + oc] = y01;
    hp[(size_t)((yb + 1) * 64 + xb) * NC + oc] = y10;
    hp[(size_t)((yb + 1) * 64 + xb + 1) * NC + oc] = y11;
}

// ---------------- helpers ----------------
__device__ __forceinline__ unsigned int fdesc(float f) {
    unsigned int u = __float_as_uint(f);
    unsigned int asc = (u & 0x80000000u) ? ~u : (u | 0x80000000u);
    return ~asc;
}
__device__ __forceinline__ void base_anchor(int a, float& y1, float& x1, float& y2, float& x2) {
    int ri = a / 3, si = a % 3;
    double ratio = (ri == 0) ? 0.5 : (ri == 1 ? 1.0 : 2.0);
    double scale = (si == 0) ? 8.0 : (si == 1 ? 16.0 : 32.0);
    double h = 16.0 * scale * sqrt(ratio);
    double w = 16.0 * scale * sqrt(1.0 / ratio);
    y1 = (float)(8.0 - h * 0.5); x1 = (float)(8.0 - w * 0.5);
    y2 = (float)(8.0 + h * 0.5); x2 = (float)(8.0 + w * 0.5);
}

// ---------------- 1x1 heads: 2-way channel-split ----------------
__global__ void __launch_bounds__(128) heads_kernel(const float* __restrict__ sw,
                                                    const float* __restrict__ sb,
                                                    const float* __restrict__ lw,
                                                    const float* __restrict__ lb,
                                                    float* __restrict__ out) {
    __shared__ float s_w[2][64][54];
    __shared__ float s_red[64][56];
    int b = blockIdx.y;
    int tid = threadIdx.x;
    int p = tid & 63, half = tid >> 6;
    int pos = blockIdx.x * 64 + p;

    float acc[54];
#pragma unroll
    for (int o = 0; o < 54; o++) acc[o] = 0.f;

    for (int ch = 0; ch < 4; ch++) {
        int c0 = half * 256 + ch * 64;
        __syncthreads();
#pragma unroll
        for (int o = 0; o < 54; o++) {
            int c = p;
            float v = (o < 18) ? sw[o * 512 + c0 + c] : lw[(o - 18) * 512 + c0 + c];
            s_w[half][c][o] = v;
        }
        __syncthreads();
        const float4* hp4 = (const float4*)(g_h + ((size_t)b * HWs + pos) * NC + c0);
        for (int c4 = 0; c4 < 16; c4++) {
            float4 v = hp4[c4];
            const float* w0 = &s_w[half][c4 * 4 + 0][0];
            const float* w1 = &s_w[half][c4 * 4 + 1][0];
            const float* w2 = &s_w[half][c4 * 4 + 2][0];
            const float* w3 = &s_w[half][c4 * 4 + 3][0];
#pragma unroll
            for (int o = 0; o < 54; o++) {
                acc[o] = fmaf(v.x, w0[o], acc[o]);
                acc[o] = fmaf(v.y, w1[o], acc[o]);
                acc[o] = fmaf(v.z, w2[o], acc[o]);
                acc[o] = fmaf(v.w, w3[o], acc[o]);
            }
        }
    }

    if (half == 1) {
#pragma unroll
        for (int o = 0; o < 54; o++) s_red[p][o] = acc[o];
    }
    __syncthreads();
    if (half == 1) return;
#pragma unroll
    for (int o = 0; o < 54; o++) acc[o] += s_red[p][o];

#pragma unroll
    for (int o = 0; o < 18; o++) acc[o] += sb[o];
#pragma unroll
    for (int j = 0; j < 36; j++) acc[18 + j] += lb[j];

    float* os = out + (size_t)(b * HWs + pos) * 18;
#pragma unroll
    for (int o = 0; o < 18; o++) os[o] = acc[o];
    float* ol = out + OFF_LOCS + (size_t)(b * HWs + pos) * 36;
#pragma unroll
    for (int j = 0; j < 36; j++) ol[j] = acc[18 + j];

    int y = pos >> 6, xq = pos & 63;
    float fy = (float)(y * 16), fx = (float)(xq * 16);
#pragma unroll
    for (int a = 0; a < 9; a++) {
        float by1, bx1, by2, bx2;
        base_anchor(a, by1, bx1, by2, bx2);
        float ay1 = fy + by1, ax1 = fx + bx1, ay2 = fy + by2, ax2 = fx + bx2;
        float hA = ay2 - ay1, wA = ax2 - ax1;
        float cy = ay1 + 0.5f * hA, cx = ax1 + 0.5f * wA;
        float dy = acc[18 + 4 * a + 0], dx = acc[18 + 4 * a + 1];
        float dh = acc[18 + 4 * a + 2], dw = acc[18 + 4 * a + 3];
        float cty = dy * hA + cy, ctx = dx * wA + cx;
        float th = expf(dh) * hA, tw = expf(dw) * wA;
        float y1 = cty - 0.5f * th, x1 = ctx - 0.5f * tw;
        float y2 = cty + 0.5f * th, x2 = ctx + 0.5f * tw;
        y1 = fminf(fmaxf(y1, 0.f), 1024.f);
        y2 = fminf(fmaxf(y2, 0.f), 1024.f);
        x1 = fminf(fmaxf(x1, 0.f), 1024.f);
        x2 = fminf(fmaxf(x2, 0.f), 1024.f);
        bool valid = (y2 - y1 >= 16.f) && (x2 - x1 >= 16.f);

        float s0 = acc[2 * a], s1 = acc[2 * a + 1];
        float m = fmaxf(s0, s1);
        float e0 = expf(s0 - m), e1 = expf(s1 - m);
        float fg = e1 / (e0 + e1);
        float skey = valid ? fg : -INFINITY;

        int r = pos * 9 + a;
        size_t ro = ((size_t)b * NA + r) * 4;
        g_rois[ro + 0] = y1; g_rois[ro + 1] = x1;
        g_rois[ro + 2] = y2; g_rois[ro + 3] = x2;
        g_valid[b * NA + r] = valid ? 1 : 0;
        g_keys[(size_t)b * NSORT + r] = ((u64)fdesc(skey) << 32) | (unsigned)r;
    }
}

// ---------------- fused aux ----------------
__global__ void aux_kernel(float* __restrict__ out) {
    int gid = blockIdx.x * blockDim.x + threadIdx.x;
    int per = NSORT - NA;
    if (gid < NB * per) {
        int b = gid / per, i = NA + gid % per;
        g_keys[(size_t)b * NSORT + i] = ~0ull;
    }
    if (gid < NA) {
        int p = gid / 9, a = gid % 9;
        int y = p / 64, x = p % 64;
        float by1, bx1, by2, bx2;
        base_anchor(a, by1, bx1, by2, bx2);
        float fy = (float)(y * 16), fx = (float)(x * 16);
        float* o = out + OFF_ANCH + (size_t)gid * 4;
        o[0] = fy + by1; o[1] = fx + bx1; o[2] = fy + by2; o[3] = fx + bx2;
    }
    if (gid < NB * NOUTP * 4) out[OFF_ROIS + gid] = 0.f;
    if (gid < NB * NOUTP) out[OFF_INDS + gid] = (float)(gid / NOUTP);
    if (gid < NB * NIN) g_keep[gid] = 0;
}

// ---------------- bitonic sort ----------------
__global__ void __launch_bounds__(1024) bitonic_local_sort() {
    __shared__ u64 s[4096];
    int base = blockIdx.x * 4096;
#pragma unroll
    for (int m = 0; m < 4; m++) s[threadIdx.x + 1024 * m] = g_keys[base + threadIdx.x + 1024 * m];
    for (int k = 2; k <= 4096; k <<= 1) {
        for (int j = k >> 1; j > 0; j >>= 1) {
            __syncthreads();
#pragma unroll
            for (int m = 0; m < 4; m++) {
                int i = threadIdx.x + 1024 * m;
                int p = i ^ j;
                if (p > i) {
                    int lidx = (base + i) & (NSORT - 1);
                    bool asc = ((lidx & k) == 0);
                    u64 av = s[i], bv = s[p];
                    if (asc ? (av > bv) : (av < bv)) { s[i] = bv; s[p] = av; }
                }
            }
        }
    }
    __syncthreads();
#pragma unroll
    for (int m = 0; m < 4; m++) g_keys[base + threadIdx.x + 1024 * m] = s[threadIdx.x + 1024 * m];
}

__global__ void __launch_bounds__(256) bitonic_global_step(int k, int j) {
    int gid = blockIdx.x * blockDim.x + threadIdx.x;
    int seg = gid >> 16, idx = gid & (NSORT - 1);
    int p = idx ^ j;
    if (p > idx) {
        bool asc = ((idx & k) == 0);
        u64* bptr = g_keys + ((size_t)seg << 16);
        u64 av = bptr[idx], bv = bptr[p];
        if (asc ? (av > bv) : (av < bv)) { bptr[idx] = bv; bptr[p] = av; }
    }
}

__global__ void __launch_bounds__(1024) bitonic_local_merge(int k) {
    __shared__ u64 s[4096];
    int base = blockIdx.x * 4096;
    bool asc = (((base & (NSORT - 1)) & k) == 0);
#pragma unroll
    for (int m = 0; m < 4; m++) s[threadIdx.x + 1024 * m] = g_keys[base + threadIdx.x + 1024 * m];
    for (int j = 2048; j > 0; j >>= 1) {
        __syncthreads();
#pragma unroll
        for (int m = 0; m < 4; m++) {
            int i = threadIdx.x + 1024 * m;
            int p = i ^ j;
            if (p > i) {
                u64 av = s[i], bv = s[p];
                if (asc ? (av > bv) : (av < bv)) { s[i] = bv; s[p] = av; }
            }
        }
    }
    __syncthreads();
#pragma unroll
    for (int m = 0; m < 4; m++) g_keys[base + threadIdx.x + 1024 * m] = s[threadIdx.x + 1024 * m];
}

__global__ void gather_kernel() {
    int gid = blockIdx.x * blockDim.x + threadIdx.x;
    if (gid >= NB * NIN) return;
    int b = gid / NIN, i = gid % NIN;
    u64 key = g_keys[(size_t)b * NSORT + i];
    unsigned r = (unsigned)(key & 0xffffffffu);
    size_t src = ((size_t)b * NA + r) * 4;
    size_t dst = ((size_t)b * NPAD + i) * 4;
    g_rois_s[dst + 0] = g_rois[src + 0];
    g_rois_s[dst + 1] = g_rois[src + 1];
    g_rois_s[dst + 2] = g_rois[src + 2];
    g_rois_s[dst + 3] = g_rois[src + 3];
    g_valid_s[b * NPAD + i] = g_valid[b * NA + r];
}

__global__ void __launch_bounds__(64) mask_kernel() {
    int rb = blockIdx.x, cb = blockIdx.y, b = blockIdx.z;
    if (cb < rb) return;
    __shared__ float4 sj[64];
    int u = threadIdx.x;
    const float4* rs = (const float4*)g_rois_s;
    sj[u] = rs[(size_t)b * NPAD + cb * 64 + u];
    __syncthreads();
    int i = rb * 64 + u;
    if (i >= NIN) return;
    float4 bi = rs[(size_t)b * NPAD + i];
    float ai = (bi.z - bi.x) * (bi.w - bi.y);
    u64 bits = 0;
#pragma unroll 8
    for (int q = 0; q < 64; q++) {
        int jj = cb * 64 + q;
        if (jj > i) {
            float4 bj = sj[q];
            float yy1 = fmaxf(bi.x, bj.x), xx1 = fmaxf(bi.y, bj.y);
            float yy2 = fminf(bi.z, bj.z), xx2 = fminf(bi.w, bj.w);
            float inter = fmaxf(yy2 - yy1, 0.f) * fmaxf(xx2 - xx1, 0.f);
            float aj = (bj.z - bj.x) * (bj.w - bj.y);
            float iou = inter / (ai + aj - inter + 1e-9f);
            if (iou > 0.7f) bits |= (1ull << q);
        }
    }
    g_mask[((size_t)b * NIN + i) * NWRD + cb] = bits;
}

// ---------------- greedy NMS scan with early exit ----------------
__global__ void __launch_bounds__(32) nms_scan_kernel() {
    int b = blockIdx.x;
    int lane = threadIdx.x;
    const u64* mask = g_mask + (size_t)b * NIN * NWRD;
    const unsigned char* vs = g_valid_s + b * NPAD;
    unsigned char* keep = g_keep + b * NIN;
    int w0 = lane, w1 = lane + 32, w2 = lane + 64;
    bool has2 = (w2 < NWRD);
    u64 r0 = 0, r1 = 0, r2 = 0;
    u64 bufA[8][3], bufB[8][3];
    unsigned char vA[8], vB[8];
    int kept = 0;
#pragma unroll
    for (int t = 0; t < 8; t++) {
        const u64* row = mask + (size_t)t * NWRD;
        bufA[t][0] = row[w0]; bufA[t][1] = row[w1];
        bufA[t][2] = has2 ? row[w2] : 0;
        vA[t] = vs[t];
    }
    for (int base = 0; base < NIN; base += 16) {
#pragma unroll
        for (int t = 0; t < 8; t++) {
            int ri = base + 8 + t;
            if (ri < NIN) {
                const u64* row = mask + (size_t)ri * NWRD;
                bufB[t][0] = row[w0]; bufB[t][1] = row[w1];
                bufB[t][2] = has2 ? row[w2] : 0;
                vB[t] = vs[ri];
            } else { bufB[t][0] = bufB[t][1] = bufB[t][2] = 0; vB[t] = 0; }
        }
#pragma unroll
        for (int t = 0; t < 8; t++) {
            int i = base + t;
            int iw = i >> 6;
            int sel = iw >> 5, owner = iw & 31;
            u64 myw = (sel == 0) ? r0 : ((sel == 1) ? r1 : r2);
            u64 wv = __shfl_sync(0xffffffffu, myw, owner);
            bool alive = vA[t] && !((wv >> (i & 63)) & 1ull);
            if (alive) {
                r0 |= bufA[t][0]; r1 |= bufA[t][1]; r2 |= bufA[t][2];
                kept++;
                if (lane == 0) keep[i] = 1;
            }
        }
        if (kept >= NOUTP) return;
#pragma unroll
        for (int t = 0; t < 8; t++) {
            int ri = base + 16 + t;
            if (ri < NIN) {
                const u64* row = mask + (size_t)ri * NWRD;
                bufA[t][0] = row[w0]; bufA[t][1] = row[w1];
                bufA[t][2] = has2 ? row[w2] : 0;
                vA[t] = vs[ri];
            } else { bufA[t][0] = bufA[t][1] = bufA[t][2] = 0; vA[t] = 0; }
        }
#pragma unroll
        for (int t = 0; t < 8; t++) {
            int i = base + 8 + t;
            if (i >= NIN) break;
            int iw = i >> 6;
            int sel = iw >> 5, owner = iw & 31;
            u64 myw = (sel == 0) ? r0 : ((sel == 1) ? r1 : r2);
            u64 wv = __shfl_sync(0xffffffffu, myw, owner);
            bool alive = vB[t] && !((wv >> (i & 63)) & 1ull);
            if (alive) {
                r0 |= bufB[t][0]; r1 |= bufB[t][1]; r2 |= bufB[t][2];
                kept++;
                if (lane == 0) keep[i] = 1;
            }
        }
        if (kept >= NOUTP) return;
    }
}

__global__ void __launch_bounds__(256) finalize_kernel(float* __restrict__ out) {
    int b = blockIdx.x;
    int tid = threadIdx.x;
    __shared__ int ssum[256];
    const unsigned char* keep = g_keep + b * NIN;
    unsigned char kl[24];
    int start = tid * 24;
    int cnt = 0;
#pragma unroll
    for (int t = 0; t < 24; t++) {
        int i = start + t;
        kl[t] = (i < NIN) ? keep[i] : 0;
        cnt += kl[t];
    }
    ssum[tid] = cnt;
    __syncthreads();
    for (int off = 1; off < 256; off <<= 1) {
        int v = (tid >= off) ? ssum[tid - off] : 0;
        __syncthreads();
        ssum[tid] += v;
        __syncthreads();
    }
    int r = ssum[tid] - cnt;
    const float4* rs = (const float4*)g_rois_s;
#pragma unroll
    for (int t = 0; t < 24; t++) {
        if (kl[t]) {
            if (r < NOUTP) {
                int i = start + t;
                float4 bx = rs[(size_t)b * NPAD + i];
                float* o = out + OFF_ROIS + (size_t)(b * NOUTP + r) * 4;
                o[0] = bx.x; o[1] = bx.y; o[2] = bx.z; o[3] = bx.w;
            }
            r++;
        }
    }
}

// ---------------- launch ----------------
extern "C" void kernel_launch(void* const* d_in, const int* in_sizes, int n_in,
                              void* d_out, int out_size) {
    const float* x       = (const float*)d_in[0];
    const float* conv_w  = (const float*)d_in[1];
    const float* conv_b  = (const float*)d_in[2];
    const float* score_w = (const float*)d_in[3];
    const float* score_b = (const float*)d_in[4];
    const float* loc_w   = (const float*)d_in[5];
    const float* loc_b   = (const float*)d_in[6];
    float* out = (float*)d_out;

    filter_transform_kernel<<<(NC * NC + 255) / 256, 256>>>(conv_w);
    input_transform_kernel<<<(NB * NC * NTIL + 255) / 256, 256>>>(x);
    wino_gemm_kernel<<<dim3(8, 4, NB * 16), 256>>>();
    output_transform_kernel<<<(NB * NTIL * NC + 255) / 256, 256>>>(conv_b);

    heads_kernel<<<dim3(64, NB), 128>>>(score_w, score_b, loc_w, loc_b, out);
    aux_kernel<<<448, 256>>>(out);

    bitonic_local_sort<<<NB * NSORT / 4096, 1024>>>();
    for (int k = 8192; k <= NSORT; k <<= 1) {
        for (int j = k >> 1; j >= 4096; j >>= 1)
            bitonic_global_step<<<NB * NSORT / 256, 256>>>(k, j);
        bitonic_local_merge<<<NB * NSORT / 4096, 1024>>>(k);
    }

    gather_kernel<<<(NB * NIN + 255) / 256, 256>>>();
    mask_kernel<<<dim3(NWRD, NWRD, NB), 64>>>();
    nms_scan_kernel<<<NB, 32>>>();
    finalize_kernel<<<NB, 256>>>(out);
}